// round 5
// baseline (speedup 1.0000x reference)
#include <cuda_runtime.h>
#include <math.h>

#define S 2048
#define B 2
#define D 2048
#define H 16
#define KV 4
#define HD 128
#define ROWS (S*B)              // 4096

// Scratch (allocation-free rule)
__device__ float g_q[ROWS*H*HD];    // 32MB
__device__ float g_k[ROWS*KV*HD];   // 8MB
__device__ float g_v[ROWS*KV*HD];   // 8MB
__device__ float g_o[ROWS*H*HD];    // 32MB
__device__ float g_sc[S*S];         // 16MB, one (b,h) slice of scores/probs

// ---------------------------------------------------------------------------
// Textbook GEMM: C[M,N] = A[M,K] @ W[K,N], row-major.
// ---------------------------------------------------------------------------
__global__ void __launch_bounds__(1024) gemm32(
    const float* __restrict__ A, const float* __restrict__ W,
    float* __restrict__ C, int M, int N, int K)
{
    __shared__ float As[32][33];
    __shared__ float Bs[32][33];
    const int tx = threadIdx.x, ty = threadIdx.y;
    const int row = blockIdx.y * 32 + ty;
    const int col = blockIdx.x * 32 + tx;
    float acc = 0.0f;
    for (int k0 = 0; k0 < K; k0 += 32) {
        As[ty][tx] = A[(size_t)row * K + k0 + tx];
        Bs[ty][tx] = W[(size_t)(k0 + ty) * N + col];
        __syncthreads();
#pragma unroll
        for (int kk = 0; kk < 32; kk++)
            acc += As[ty][kk] * Bs[kk][tx];
        __syncthreads();
    }
    C[(size_t)row * N + col] = acc;
}

// ---------------------------------------------------------------------------
// RoPE in-place. SINGLE CHANGE THIS ROUND: angle negated (conjugate rotation)
//   ang = -s * 10000^(-dd/64)
//   out[dd]    = u1*cos(ang) - u2*sin(ang)
//   out[dd+64] = u2*cos(ang) + u1*sin(ang)
// (equivalently: out1 = u1*c + u2*s, out2 = u2*c - u1*s with positive angle)
// ---------------------------------------------------------------------------
__global__ void rope(float* p, int nheads)
{
    int i = blockIdx.x * 256 + threadIdx.x;
    int total = ROWS * nheads * 64;
    if (i >= total) return;
    int dd   = i % 64;
    int t    = i / 64;
    int head = t % nheads;
    int row  = t / nheads;
    int s    = row / B;

    float e    = (float)(2 * dd) / 128.0f;       // exact fp32
    float invf = 1.0f / powf(10000.0f, e);
    float ang  = -(float)s * invf;               // <<< negated angle
    float c, sn;
    sincosf(ang, &c, &sn);

    float* base = p + ((size_t)row * nheads + head) * HD;
    float u1 = base[dd];
    float u2 = base[dd + 64];
    base[dd]      = u1 * c - u2 * sn;
    base[dd + 64] = u2 * c + u1 * sn;
}

// ---------------------------------------------------------------------------
// Scores for one (b,h) slice: g_sc[qi][ki] = (q[qi]·k[ki]) * 1/sqrt(128)
// ---------------------------------------------------------------------------
__global__ void __launch_bounds__(1024) scores_kernel(int b, int h, int kvh)
{
    __shared__ float Qs[32][33];
    __shared__ float Ks[32][33];
    const int tx = threadIdx.x, ty = threadIdx.y;
    const int qi = blockIdx.y * 32 + ty;
    const int ki = blockIdx.x * 32 + tx;
    float acc = 0.0f;
    for (int k0 = 0; k0 < HD; k0 += 32) {
        int qrow = blockIdx.y * 32 + ty;
        int krow = blockIdx.x * 32 + ty;
        Qs[ty][tx] = g_q[(((size_t)qrow * B + b) * H  + h  ) * HD + k0 + tx];
        Ks[ty][tx] = g_k[(((size_t)krow * B + b) * KV + kvh) * HD + k0 + tx];
        __syncthreads();
#pragma unroll
        for (int kk = 0; kk < 32; kk++)
            acc += Qs[ty][kk] * Ks[tx][kk];
        __syncthreads();
    }
    g_sc[(size_t)qi * S + ki] = acc * 0.08838834764831845f;
}

// ---------------------------------------------------------------------------
// Literal two-pass softmax per row over valid keys [0..qi]; zero the rest.
// ---------------------------------------------------------------------------
__global__ void __launch_bounds__(256) softmax_kernel()
{
    __shared__ float red[256];
    const int qi = blockIdx.x;
    const int n  = qi + 1;
    const int t  = threadIdx.x;
    float* rowp = g_sc + (size_t)qi * S;

    float mx = -3.4e38f;
    for (int j = t; j < n; j += 256) mx = fmaxf(mx, rowp[j]);
    red[t] = mx;
    __syncthreads();
    for (int s = 128; s; s >>= 1) {
        if (t < s) red[t] = fmaxf(red[t], red[t + s]);
        __syncthreads();
    }
    mx = red[0];
    __syncthreads();

    float sum = 0.0f;
    for (int j = t; j < n; j += 256) sum += expf(rowp[j] - mx);
    red[t] = sum;
    __syncthreads();
    for (int s = 128; s; s >>= 1) {
        if (t < s) red[t] += red[t + s];
        __syncthreads();
    }
    const float inv = 1.0f / red[0];

    for (int j = t; j < n; j += 256) rowp[j] = expf(rowp[j] - mx) * inv;
    for (int j = n + t; j < S; j += 256) rowp[j] = 0.0f;
}

// ---------------------------------------------------------------------------
// P @ V for one (b,h) slice: g_o[qi, b, h, d] = sum_j P[qi][j] * v[j][d]
// ---------------------------------------------------------------------------
__global__ void __launch_bounds__(1024) pv_kernel(int b, int h, int kvh)
{
    __shared__ float Ps[32][33];
    __shared__ float Vs[32][33];
    const int tx = threadIdx.x, ty = threadIdx.y;
    const int qi = blockIdx.y * 32 + ty;
    const int d  = blockIdx.x * 32 + tx;
    float acc = 0.0f;
    for (int k0 = 0; k0 < S; k0 += 32) {
        Ps[ty][tx] = g_sc[(size_t)qi * S + k0 + tx];
        Vs[ty][tx] = g_v[(((size_t)(k0 + ty) * B + b) * KV + kvh) * HD + d];
        __syncthreads();
#pragma unroll
        for (int kk = 0; kk < 32; kk++)
            acc += Ps[ty][kk] * Vs[kk][tx];
        __syncthreads();
    }
    g_o[(((size_t)qi * B + b) * H + h) * HD + d] = acc;
}

// ---------------------------------------------------------------------------
// Launch
// ---------------------------------------------------------------------------
extern "C" void kernel_launch(void* const* d_in, const int* in_sizes, int n_in,
                              void* d_out, int out_size)
{
    int ix = -1, ik = -1, iv = -1, ia = -1, ib = -1;
    for (int i = 0; i < n_in; i++) {
        if (in_sizes[i] == 8388608) { ix = i; }
        else if (in_sizes[i] == 1048576) { if (ik < 0) ik = i; else iv = i; }
        else if (in_sizes[i] == 4194304) { if (ia < 0) ia = i; else ib = i; }
    }
    int iq, io;
    if (ix == 0) { iq = ia; io = ib; }   // dict order: x,Wq,Wk,Wv,Wo
    else         { io = ia; iq = ib; }

    const float* x  = (const float*)d_in[ix];
    const float* Wq = (const float*)d_in[iq];
    const float* Wk = (const float*)d_in[ik];
    const float* Wv = (const float*)d_in[iv];
    const float* Wo = (const float*)d_in[io];
    float* out = (float*)d_out;

    float* gq; cudaGetSymbolAddress((void**)&gq, g_q);
    float* gk; cudaGetSymbolAddress((void**)&gk, g_k);
    float* gv; cudaGetSymbolAddress((void**)&gv, g_v);
    float* go; cudaGetSymbolAddress((void**)&go, g_o);

    dim3 blk(32, 32);
    // Projections
    gemm32<<<dim3(D     / 32, ROWS / 32), blk>>>(x, Wq, gq, ROWS, D,     D);
    gemm32<<<dim3(KV*HD / 32, ROWS / 32), blk>>>(x, Wk, gk, ROWS, KV*HD, D);
    gemm32<<<dim3(KV*HD / 32, ROWS / 32), blk>>>(x, Wv, gv, ROWS, KV*HD, D);

    // RoPE (negated-angle experiment)
    rope<<<(ROWS * H  * 64 + 255) / 256, 256>>>(gq, H);
    rope<<<(ROWS * KV * 64 + 255) / 256, 256>>>(gk, KV);

    // Literal attention, one (b,h) slice at a time
    for (int b = 0; b < B; b++) {
        for (int h = 0; h < H; h++) {
            int kvh = h / 4;                      // N_REP = 4
            scores_kernel <<<dim3(S / 32, S / 32), blk>>>(b, h, kvh);
            softmax_kernel<<<S, 256>>>();
            pv_kernel     <<<dim3(HD / 32, S / 32), blk>>>(b, h, kvh);
        }
    }

    // Output projection
    gemm32<<<dim3(D / 32, ROWS / 32), blk>>>(go, Wo, out, ROWS, D, D);
}

// round 6
// speedup vs baseline: 5.7685x; 5.7685x over previous
#include <cuda_runtime.h>
#include <math.h>

// Problem constants
#define S_LEN 2048
#define BATCH 2
#define DMODEL 2048
#define NH 16
#define NKV 4
#define HD 128
#define SB (S_LEN*BATCH)          // 4096 rows (s*B+b)
#define QW (NH*HD)                // 2048
#define KW (NKV*HD)               // 512

// Scratch (allocation-free rule: __device__ globals)
__device__ float g_q[SB*QW];
__device__ float g_k[SB*KW];
__device__ float g_v[SB*KW];
__device__ float g_o[SB*QW];

// ---------------------------------------------------------------------------
// fp32 tiled GEMM body: C[m0.., n0..] = A[m0..][:] * B[:][n0..]
// BM=BN=128, BK=16, 256 threads, 8x8 per-thread microtile.
// ---------------------------------------------------------------------------
__device__ __forceinline__ void gemm_tile(
    const float* __restrict__ A, int lda,
    const float* __restrict__ B, int ldb,
    float* __restrict__ C, int ldc,
    int K, int m0, int n0)
{
    __shared__ float As[16][128];   // transposed: As[k][m]
    __shared__ float Bs[16][128];   // Bs[k][n]
    const int tid = threadIdx.x;
    const int tx = tid & 15;
    const int ty = tid >> 4;

    float acc[8][8];
#pragma unroll
    for (int i = 0; i < 8; i++)
#pragma unroll
        for (int j = 0; j < 8; j++) acc[i][j] = 0.0f;

    for (int k0 = 0; k0 < K; k0 += 16) {
#pragma unroll
        for (int t = 0; t < 2; t++) {
            int idx = tid + t * 256;
            int arow = idx >> 2;
            int ac   = (idx & 3) << 2;
            float4 va = *(const float4*)(A + (size_t)(m0 + arow) * lda + k0 + ac);
            As[ac + 0][arow] = va.x;
            As[ac + 1][arow] = va.y;
            As[ac + 2][arow] = va.z;
            As[ac + 3][arow] = va.w;
            int brow = idx >> 5;
            int bc   = (idx & 31) << 2;
            *(float4*)&Bs[brow][bc] =
                *(const float4*)(B + (size_t)(k0 + brow) * ldb + n0 + bc);
        }
        __syncthreads();
#pragma unroll
        for (int kk = 0; kk < 16; kk++) {
            float rm[8], rn[8];
            *(float4*)&rm[0] = *(const float4*)&As[kk][ty * 8];
            *(float4*)&rm[4] = *(const float4*)&As[kk][ty * 8 + 4];
            *(float4*)&rn[0] = *(const float4*)&Bs[kk][tx * 8];
            *(float4*)&rn[4] = *(const float4*)&Bs[kk][tx * 8 + 4];
#pragma unroll
            for (int i = 0; i < 8; i++)
#pragma unroll
                for (int j = 0; j < 8; j++)
                    acc[i][j] += rm[i] * rn[j];
        }
        __syncthreads();
    }
#pragma unroll
    for (int i = 0; i < 8; i++) {
        float* cp = C + (size_t)(m0 + ty * 8 + i) * ldc + n0 + tx * 8;
        float4 v0 = make_float4(acc[i][0], acc[i][1], acc[i][2], acc[i][3]);
        float4 v1 = make_float4(acc[i][4], acc[i][5], acc[i][6], acc[i][7]);
        *(float4*)cp       = v0;
        *(float4*)(cp + 4) = v1;
    }
}

// Fused QKV projection: logical N = 2048(Q) + 512(K) + 512(V) = 3072 -> 24 n-blocks
__global__ void __launch_bounds__(256) qkv_kernel(
    const float* __restrict__ x,
    const float* __restrict__ Wq,
    const float* __restrict__ Wk,
    const float* __restrict__ Wv)
{
    int ncol0 = blockIdx.x * 128;
    int m0    = blockIdx.y * 128;
    const float* Bp;
    float* Cp;
    int ldn, n0;
    if (ncol0 < 2048)      { Bp = Wq; Cp = g_q; ldn = QW; n0 = ncol0;        }
    else if (ncol0 < 2560) { Bp = Wk; Cp = g_k; ldn = KW; n0 = ncol0 - 2048; }
    else                   { Bp = Wv; Cp = g_v; ldn = KW; n0 = ncol0 - 2560; }
    gemm_tile(x, DMODEL, Bp, ldn, Cp, ldn, DMODEL, m0, n0);
}

// Output projection: d_out = g_o @ Wo
__global__ void __launch_bounds__(256) out_kernel(
    const float* __restrict__ Wo, float* __restrict__ out)
{
    gemm_tile(g_o, QW, Wo, DMODEL, out, DMODEL, QW, blockIdx.y * 128, blockIdx.x * 128);
}

// ---------------------------------------------------------------------------
// RoPE (in-place), with the VALIDATED negated angle:
//   ang = -s * 10000^(-dd/64)
//   out[dd]    = u1*cos - u2*sin ; out[dd+64] = u2*cos + u1*sin
// ---------------------------------------------------------------------------
__global__ void __launch_bounds__(256) rope_kernel(int which)
{
    float* p     = which ? g_k : g_q;
    const int nh = which ? NKV : NH;
    int idx  = blockIdx.x * 256 + threadIdx.x;
    int dd   = idx & 63;
    int rest = idx >> 6;
    int head = rest & (nh - 1);
    int row  = rest / nh;           // row = s*BATCH + b
    if (row >= SB) return;
    int s = row >> 1;               // BATCH == 2

    float e    = (float)(2 * dd) / 128.0f;
    float invf = 1.0f / powf(10000.0f, e);
    float ang  = -(float)s * invf;          // validated sign
    float c, sn;
    sincosf(ang, &c, &sn);

    float* base = p + (size_t)row * (nh * HD) + head * HD;
    float u1 = base[dd];
    float u2 = base[dd + 64];
    base[dd]      = u1 * c - u2 * sn;
    base[dd + 64] = u2 * c + u1 * sn;
}

// ---------------------------------------------------------------------------
// Flash attention (causal, GQA). Grid: (32 q-tiles, B*H=32). 256 threads.
// Per block: 64 q rows; warp w owns rows w*8..w*8+7.
// ---------------------------------------------------------------------------
#define KTS 65   // padded row stride of transposed K tile

__global__ void __launch_bounds__(256) flash_kernel()
{
    extern __shared__ float sm[];
    float* sQ  = sm;                     // 64*128
    float* sKT = sQ  + 64 * 128;         // 128*KTS (transposed K)
    float* sV  = sKT + 128 * KTS;        // 64*128
    float* sS  = sV  + 64 * 128;         // 64*64 (probs)

    const int qt  = blockIdx.x;
    const int bh  = blockIdx.y;
    const int b   = bh >> 4;
    const int h   = bh & 15;
    const int kvh = h >> 2;              // N_REP = 4
    const int tid = threadIdx.x;
    const int lane = tid & 31;
    const int w    = tid >> 5;

    for (int idx = tid; idx < 64 * 32; idx += 256) {
        int r = idx >> 5;
        int c = (idx & 31) << 2;
        int s = qt * 64 + r;
        *(float4*)&sQ[r * 128 + c] =
            *(const float4*)&g_q[((size_t)s * BATCH + b) * QW + h * HD + c];
    }

    float m_i[8], l_i[8], oa[8][4];
#pragma unroll
    for (int rr = 0; rr < 8; rr++) {
        m_i[rr] = -1e30f; l_i[rr] = 0.0f;
        oa[rr][0] = oa[rr][1] = oa[rr][2] = oa[rr][3] = 0.0f;
    }
    const float sc = 0.08838834764831845f;   // 1/sqrt(128)

    for (int kt = 0; kt <= qt; kt++) {
        __syncthreads();
        for (int idx = tid; idx < 64 * 32; idx += 256) {
            int j = idx >> 5;
            int c = (idx & 31) << 2;
            size_t ga = ((size_t)(kt * 64 + j) * BATCH + b) * KW + kvh * HD + c;
            float4 vk = *(const float4*)&g_k[ga];
            sKT[(c + 0) * KTS + j] = vk.x;
            sKT[(c + 1) * KTS + j] = vk.y;
            sKT[(c + 2) * KTS + j] = vk.z;
            sKT[(c + 3) * KTS + j] = vk.w;
            *(float4*)&sV[j * 128 + c] = *(const float4*)&g_v[ga];
        }
        __syncthreads();

        float s0[8], s1[8];
#pragma unroll
        for (int rr = 0; rr < 8; rr++) { s0[rr] = 0.0f; s1[rr] = 0.0f; }
        for (int c = 0; c < 128; c += 4) {
            float k0[4], k1[4];
#pragma unroll
            for (int i = 0; i < 4; i++) {
                k0[i] = sKT[(c + i) * KTS + lane];
                k1[i] = sKT[(c + i) * KTS + lane + 32];
            }
#pragma unroll
            for (int rr = 0; rr < 8; rr++) {
                const float4 qv = *(const float4*)&sQ[(w * 8 + rr) * 128 + c];
                s0[rr] += qv.x * k0[0] + qv.y * k0[1] + qv.z * k0[2] + qv.w * k0[3];
                s1[rr] += qv.x * k1[0] + qv.y * k1[1] + qv.z * k1[2] + qv.w * k1[3];
            }
        }

        const bool diag = (kt == qt);
#pragma unroll
        for (int rr = 0; rr < 8; rr++) {
            int r = w * 8 + rr;
            float v0 = s0[rr] * sc;
            float v1 = s1[rr] * sc;
            if (diag) {
                int qi = qt * 64 + r;
                if (kt * 64 + lane      > qi) v0 = -1e30f;
                if (kt * 64 + lane + 32 > qi) v1 = -1e30f;
            }
            float mx = fmaxf(v0, v1);
#pragma unroll
            for (int off = 16; off; off >>= 1)
                mx = fmaxf(mx, __shfl_xor_sync(0xffffffffu, mx, off));
            float mnew = fmaxf(m_i[rr], mx);
            float p0 = expf(v0 - mnew);
            float p1 = expf(v1 - mnew);
            float ps = p0 + p1;
#pragma unroll
            for (int off = 16; off; off >>= 1)
                ps += __shfl_xor_sync(0xffffffffu, ps, off);
            float corr = expf(m_i[rr] - mnew);
            l_i[rr] = l_i[rr] * corr + ps;
            m_i[rr] = mnew;
            oa[rr][0] *= corr; oa[rr][1] *= corr;
            oa[rr][2] *= corr; oa[rr][3] *= corr;
            sS[r * 64 + lane]      = p0;
            sS[r * 64 + lane + 32] = p1;
        }
        __syncwarp();

        for (int j = 0; j < 64; j++) {
            const float4 vv = *(const float4*)&sV[j * 128 + lane * 4];
#pragma unroll
            for (int rr = 0; rr < 8; rr++) {
                float p = sS[(w * 8 + rr) * 64 + j];
                oa[rr][0] += p * vv.x;
                oa[rr][1] += p * vv.y;
                oa[rr][2] += p * vv.z;
                oa[rr][3] += p * vv.w;
            }
        }
    }

#pragma unroll
    for (int rr = 0; rr < 8; rr++) {
        int s = qt * 64 + w * 8 + rr;
        float invl = 1.0f / l_i[rr];
        float4 ov = make_float4(oa[rr][0] * invl, oa[rr][1] * invl,
                                oa[rr][2] * invl, oa[rr][3] * invl);
        *(float4*)&g_o[((size_t)s * BATCH + b) * QW + h * HD + lane * 4] = ov;
    }
}

// ---------------------------------------------------------------------------
// Launch
// ---------------------------------------------------------------------------
extern "C" void kernel_launch(void* const* d_in, const int* in_sizes, int n_in,
                              void* d_out, int out_size)
{
    int ix = -1, ik = -1, iv = -1, ia = -1, ib = -1;
    for (int i = 0; i < n_in; i++) {
        if (in_sizes[i] == 8388608) { ix = i; }
        else if (in_sizes[i] == 1048576) { if (ik < 0) ik = i; else iv = i; }
        else if (in_sizes[i] == 4194304) { if (ia < 0) ia = i; else ib = i; }
    }
    int iq, io;
    if (ix == 0) { iq = ia; io = ib; }   // dict order: x,Wq,Wk,Wv,Wo (confirmed)
    else         { io = ia; iq = ib; }

    const float* x  = (const float*)d_in[ix];
    const float* Wq = (const float*)d_in[iq];
    const float* Wk = (const float*)d_in[ik];
    const float* Wv = (const float*)d_in[iv];
    const float* Wo = (const float*)d_in[io];
    float* out = (float*)d_out;

    qkv_kernel<<<dim3(24, 32), 256>>>(x, Wq, Wk, Wv);

    rope_kernel<<<(SB * NH  * 64) / 256, 256>>>(0);
    rope_kernel<<<(SB * NKV * 64) / 256, 256>>>(1);

    const int FLASH_SMEM = (64 * 128 + 128 * KTS + 64 * 128 + 64 * 64) * (int)sizeof(float);
    cudaFuncSetAttribute(flash_kernel, cudaFuncAttributeMaxDynamicSharedMemorySize, FLASH_SMEM);
    flash_kernel<<<dim3(32, 32), 256, FLASH_SMEM>>>();

    out_kernel<<<dim3(16, 32), 256>>>(Wo, out);
}

// round 7
// speedup vs baseline: 8.6701x; 1.5030x over previous
#include <cuda_runtime.h>
#include <math.h>
#include <stdint.h>

// Problem constants
#define S_LEN 2048
#define BATCH 2
#define DMODEL 2048
#define NH 16
#define NKV 4
#define HD 128
#define SB (S_LEN*BATCH)          // 4096 rows (s*B+b)
#define QW (NH*HD)                // 2048
#define KW (NKV*HD)               // 512

// Scratch
__device__ float g_q[SB*QW];
__device__ float g_k[SB*KW];
__device__ float g_v[SB*KW];
__device__ float g_o[SB*QW];

// ---------------------------------------------------------------------------
// tf32 helpers
// ---------------------------------------------------------------------------
__device__ __forceinline__ uint32_t f2tf32(float f) {
    uint32_t r;
    asm("cvt.rna.tf32.f32 %0, %1;" : "=r"(r) : "f"(f));
    return r;
}

__device__ __forceinline__ void mma_tf32(float* c,
    uint32_t a0, uint32_t a1, uint32_t a2, uint32_t a3,
    uint32_t b0, uint32_t b1)
{
    asm volatile(
        "mma.sync.aligned.m16n8k8.row.col.f32.tf32.tf32.f32 "
        "{%0,%1,%2,%3}, {%4,%5,%6,%7}, {%8,%9}, {%0,%1,%2,%3};"
        : "+f"(c[0]), "+f"(c[1]), "+f"(c[2]), "+f"(c[3])
        : "r"(a0), "r"(a1), "r"(a2), "r"(a3), "r"(b0), "r"(b1));
}

// ---------------------------------------------------------------------------
// tf32 tensor-core GEMM tile: C[m0..+128, n0..+128] = A @ B
// A row-major [M,K] (lda), B row-major [K,N] (ldb). 256 threads, 8 warps
// (2m x 4n), each warp 64x32 via 4x4 m16n8k8 tiles. BK=32.
// ---------------------------------------------------------------------------
#define BK 32
#define SSTR 132   // padded smem row stride (floats)

__device__ __forceinline__ void gemm_tc(
    const float* __restrict__ A, int lda,
    const float* __restrict__ B, int ldb,
    float* __restrict__ C, int ldc,
    int K, int m0, int n0)
{
    __shared__ uint32_t As[BK][SSTR];   // As[k][m], tf32
    __shared__ uint32_t Bs[BK][SSTR];   // Bs[k][n], tf32

    const int tid  = threadIdx.x;
    const int lane = tid & 31;
    const int wid  = tid >> 5;
    const int wm   = wid >> 2;          // 0..1 -> m offset wm*64
    const int wn   = wid & 3;           // 0..3 -> n offset wn*32
    const int g    = lane >> 2;         // 0..7
    const int t    = lane & 3;          // 0..3

    float acc[4][4][4];
#pragma unroll
    for (int mm = 0; mm < 4; mm++)
#pragma unroll
        for (int nn = 0; nn < 4; nn++)
#pragma unroll
            for (int i = 0; i < 4; i++) acc[mm][nn][i] = 0.0f;

    float4 pa[4], pb[4];

    // prefetch k-tile 0
#pragma unroll
    for (int i = 0; i < 4; i++) {
        int idx = tid + i * 256;
        int am = idx >> 3, akq = idx & 7;            // A: [m][kq*4]
        pa[i] = *(const float4*)(A + (size_t)(m0 + am) * lda + akq * 4);
        int bk = idx >> 5, bnq = idx & 31;           // B: [k][nq*4]
        pb[i] = *(const float4*)(B + (size_t)bk * ldb + n0 + bnq * 4);
    }

    for (int kt = 0; kt < K; kt += BK) {
        // commit prefetched tile to smem (tf32)
#pragma unroll
        for (int i = 0; i < 4; i++) {
            int idx = tid + i * 256;
            int am = idx >> 3, akq = idx & 7;
            As[akq * 4 + 0][am] = f2tf32(pa[i].x);
            As[akq * 4 + 1][am] = f2tf32(pa[i].y);
            As[akq * 4 + 2][am] = f2tf32(pa[i].z);
            As[akq * 4 + 3][am] = f2tf32(pa[i].w);
            int bk = idx >> 5, bnq = idx & 31;
            Bs[bk][bnq * 4 + 0] = f2tf32(pb[i].x);
            Bs[bk][bnq * 4 + 1] = f2tf32(pb[i].y);
            Bs[bk][bnq * 4 + 2] = f2tf32(pb[i].z);
            Bs[bk][bnq * 4 + 3] = f2tf32(pb[i].w);
        }
        __syncthreads();

        // prefetch next k-tile
        if (kt + BK < K) {
#pragma unroll
            for (int i = 0; i < 4; i++) {
                int idx = tid + i * 256;
                int am = idx >> 3, akq = idx & 7;
                pa[i] = *(const float4*)(A + (size_t)(m0 + am) * lda + kt + BK + akq * 4);
                int bk = idx >> 5, bnq = idx & 31;
                pb[i] = *(const float4*)(B + (size_t)(kt + BK + bk) * ldb + n0 + bnq * 4);
            }
        }

        // compute 4 k-steps of 8
#pragma unroll
        for (int ks = 0; ks < BK; ks += 8) {
            uint32_t af[4][4], bf[4][2];
#pragma unroll
            for (int mm = 0; mm < 4; mm++) {
                int mr = wm * 64 + mm * 16 + g;
                af[mm][0] = As[ks + t][mr];
                af[mm][1] = As[ks + t][mr + 8];
                af[mm][2] = As[ks + t + 4][mr];
                af[mm][3] = As[ks + t + 4][mr + 8];
            }
#pragma unroll
            for (int nn = 0; nn < 4; nn++) {
                int nc = wn * 32 + nn * 8 + g;
                bf[nn][0] = Bs[ks + t][nc];
                bf[nn][1] = Bs[ks + t + 4][nc];
            }
#pragma unroll
            for (int mm = 0; mm < 4; mm++)
#pragma unroll
                for (int nn = 0; nn < 4; nn++)
                    mma_tf32(acc[mm][nn], af[mm][0], af[mm][1], af[mm][2], af[mm][3],
                             bf[nn][0], bf[nn][1]);
        }
        __syncthreads();
    }

    // store: c0(g,2t) c1(g,2t+1) c2(g+8,2t) c3(g+8,2t+1)
#pragma unroll
    for (int mm = 0; mm < 4; mm++)
#pragma unroll
        for (int nn = 0; nn < 4; nn++) {
            int row = m0 + wm * 64 + mm * 16 + g;
            int col = n0 + wn * 32 + nn * 8 + t * 2;
            float2 lo = make_float2(acc[mm][nn][0], acc[mm][nn][1]);
            float2 hi = make_float2(acc[mm][nn][2], acc[mm][nn][3]);
            *(float2*)&C[(size_t)row * ldc + col]       = lo;
            *(float2*)&C[(size_t)(row + 8) * ldc + col] = hi;
        }
}

// Fused QKV projection
__global__ void __launch_bounds__(256) qkv_kernel(
    const float* __restrict__ x,
    const float* __restrict__ Wq,
    const float* __restrict__ Wk,
    const float* __restrict__ Wv)
{
    int ncol0 = blockIdx.x * 128;
    int m0    = blockIdx.y * 128;
    const float* Bp;
    float* Cp;
    int ldn, n0;
    if (ncol0 < 2048)      { Bp = Wq; Cp = g_q; ldn = QW; n0 = ncol0;        }
    else if (ncol0 < 2560) { Bp = Wk; Cp = g_k; ldn = KW; n0 = ncol0 - 2048; }
    else                   { Bp = Wv; Cp = g_v; ldn = KW; n0 = ncol0 - 2560; }
    gemm_tc(x, DMODEL, Bp, ldn, Cp, ldn, DMODEL, m0, n0);
}

// Output projection
__global__ void __launch_bounds__(256) out_kernel(
    const float* __restrict__ Wo, float* __restrict__ out)
{
    gemm_tc(g_o, QW, Wo, DMODEL, out, DMODEL, QW, blockIdx.y * 128, blockIdx.x * 128);
}

// ---------------------------------------------------------------------------
// RoPE (validated negated angle)
// ---------------------------------------------------------------------------
__global__ void __launch_bounds__(256) rope_kernel(int which)
{
    float* p     = which ? g_k : g_q;
    const int nh = which ? NKV : NH;
    int idx  = blockIdx.x * 256 + threadIdx.x;
    int dd   = idx & 63;
    int rest = idx >> 6;
    int head = rest & (nh - 1);
    int row  = rest / nh;
    if (row >= SB) return;
    int s = row >> 1;

    float e    = (float)(2 * dd) / 128.0f;
    float invf = 1.0f / powf(10000.0f, e);
    float ang  = -(float)s * invf;          // validated sign
    float c, sn;
    sincosf(ang, &c, &sn);

    float* base = p + (size_t)row * (nh * HD) + head * HD;
    float u1 = base[dd];
    float u2 = base[dd + 64];
    base[dd]      = u1 * c - u2 * sn;
    base[dd + 64] = u2 * c + u1 * sn;
}

// ---------------------------------------------------------------------------
// Flash attention (unchanged from round 6)
// ---------------------------------------------------------------------------
#define KTS 65

__global__ void __launch_bounds__(256) flash_kernel()
{
    extern __shared__ float sm[];
    float* sQ  = sm;
    float* sKT = sQ  + 64 * 128;
    float* sV  = sKT + 128 * KTS;
    float* sS  = sV  + 64 * 128;

    const int qt  = blockIdx.x;
    const int bh  = blockIdx.y;
    const int b   = bh >> 4;
    const int h   = bh & 15;
    const int kvh = h >> 2;
    const int tid = threadIdx.x;
    const int lane = tid & 31;
    const int w    = tid >> 5;

    for (int idx = tid; idx < 64 * 32; idx += 256) {
        int r = idx >> 5;
        int c = (idx & 31) << 2;
        int s = qt * 64 + r;
        *(float4*)&sQ[r * 128 + c] =
            *(const float4*)&g_q[((size_t)s * BATCH + b) * QW + h * HD + c];
    }

    float m_i[8], l_i[8], oa[8][4];
#pragma unroll
    for (int rr = 0; rr < 8; rr++) {
        m_i[rr] = -1e30f; l_i[rr] = 0.0f;
        oa[rr][0] = oa[rr][1] = oa[rr][2] = oa[rr][3] = 0.0f;
    }
    const float sc = 0.08838834764831845f;

    for (int kt = 0; kt <= qt; kt++) {
        __syncthreads();
        for (int idx = tid; idx < 64 * 32; idx += 256) {
            int j = idx >> 5;
            int c = (idx & 31) << 2;
            size_t ga = ((size_t)(kt * 64 + j) * BATCH + b) * KW + kvh * HD + c;
            float4 vk = *(const float4*)&g_k[ga];
            sKT[(c + 0) * KTS + j] = vk.x;
            sKT[(c + 1) * KTS + j] = vk.y;
            sKT[(c + 2) * KTS + j] = vk.z;
            sKT[(c + 3) * KTS + j] = vk.w;
            *(float4*)&sV[j * 128 + c] = *(const float4*)&g_v[ga];
        }
        __syncthreads();

        float s0[8], s1[8];
#pragma unroll
        for (int rr = 0; rr < 8; rr++) { s0[rr] = 0.0f; s1[rr] = 0.0f; }
        for (int c = 0; c < 128; c += 4) {
            float k0[4], k1[4];
#pragma unroll
            for (int i = 0; i < 4; i++) {
                k0[i] = sKT[(c + i) * KTS + lane];
                k1[i] = sKT[(c + i) * KTS + lane + 32];
            }
#pragma unroll
            for (int rr = 0; rr < 8; rr++) {
                const float4 qv = *(const float4*)&sQ[(w * 8 + rr) * 128 + c];
                s0[rr] += qv.x * k0[0] + qv.y * k0[1] + qv.z * k0[2] + qv.w * k0[3];
                s1[rr] += qv.x * k1[0] + qv.y * k1[1] + qv.z * k1[2] + qv.w * k1[3];
            }
        }

        const bool diag = (kt == qt);
#pragma unroll
        for (int rr = 0; rr < 8; rr++) {
            int r = w * 8 + rr;
            float v0 = s0[rr] * sc;
            float v1 = s1[rr] * sc;
            if (diag) {
                int qi = qt * 64 + r;
                if (kt * 64 + lane      > qi) v0 = -1e30f;
                if (kt * 64 + lane + 32 > qi) v1 = -1e30f;
            }
            float mx = fmaxf(v0, v1);
#pragma unroll
            for (int off = 16; off; off >>= 1)
                mx = fmaxf(mx, __shfl_xor_sync(0xffffffffu, mx, off));
            float mnew = fmaxf(m_i[rr], mx);
            float p0 = expf(v0 - mnew);
            float p1 = expf(v1 - mnew);
            float ps = p0 + p1;
#pragma unroll
            for (int off = 16; off; off >>= 1)
                ps += __shfl_xor_sync(0xffffffffu, ps, off);
            float corr = expf(m_i[rr] - mnew);
            l_i[rr] = l_i[rr] * corr + ps;
            m_i[rr] = mnew;
            oa[rr][0] *= corr; oa[rr][1] *= corr;
            oa[rr][2] *= corr; oa[rr][3] *= corr;
            sS[r * 64 + lane]      = p0;
            sS[r * 64 + lane + 32] = p1;
        }
        __syncwarp();

        for (int j = 0; j < 64; j++) {
            const float4 vv = *(const float4*)&sV[j * 128 + lane * 4];
#pragma unroll
            for (int rr = 0; rr < 8; rr++) {
                float p = sS[(w * 8 + rr) * 64 + j];
                oa[rr][0] += p * vv.x;
                oa[rr][1] += p * vv.y;
                oa[rr][2] += p * vv.z;
                oa[rr][3] += p * vv.w;
            }
        }
    }

#pragma unroll
    for (int rr = 0; rr < 8; rr++) {
        int s = qt * 64 + w * 8 + rr;
        float invl = 1.0f / l_i[rr];
        float4 ov = make_float4(oa[rr][0] * invl, oa[rr][1] * invl,
                                oa[rr][2] * invl, oa[rr][3] * invl);
        *(float4*)&g_o[((size_t)s * BATCH + b) * QW + h * HD + lane * 4] = ov;
    }
}

// ---------------------------------------------------------------------------
// Launch
// ---------------------------------------------------------------------------
extern "C" void kernel_launch(void* const* d_in, const int* in_sizes, int n_in,
                              void* d_out, int out_size)
{
    int ix = -1, ik = -1, iv = -1, ia = -1, ib = -1;
    for (int i = 0; i < n_in; i++) {
        if (in_sizes[i] == 8388608) { ix = i; }
        else if (in_sizes[i] == 1048576) { if (ik < 0) ik = i; else iv = i; }
        else if (in_sizes[i] == 4194304) { if (ia < 0) ia = i; else ib = i; }
    }
    int iq, io;
    if (ix == 0) { iq = ia; io = ib; }
    else         { io = ia; iq = ib; }

    const float* x  = (const float*)d_in[ix];
    const float* Wq = (const float*)d_in[iq];
    const float* Wk = (const float*)d_in[ik];
    const float* Wv = (const float*)d_in[iv];
    const float* Wo = (const float*)d_in[io];
    float* out = (float*)d_out;

    qkv_kernel<<<dim3(24, 32), 256>>>(x, Wq, Wk, Wv);

    rope_kernel<<<(SB * NH  * 64) / 256, 256>>>(0);
    rope_kernel<<<(SB * NKV * 64) / 256, 256>>>(1);

    const int FLASH_SMEM = (64 * 128 + 128 * KTS + 64 * 128 + 64 * 64) * (int)sizeof(float);
    cudaFuncSetAttribute(flash_kernel, cudaFuncAttributeMaxDynamicSharedMemorySize, FLASH_SMEM);
    flash_kernel<<<dim3(32, 32), 256, FLASH_SMEM>>>();

    out_kernel<<<dim3(16, 32), 256>>>(Wo, out);
}

// round 8
// speedup vs baseline: 10.0168x; 1.1553x over previous
#include <cuda_runtime.h>
#include <math.h>
#include <stdint.h>

// Problem constants
#define S_LEN 2048
#define BATCH 2
#define DMODEL 2048
#define NH 16
#define NKV 4
#define HD 128
#define SB (S_LEN*BATCH)          // 4096 rows (s*B+b)
#define QW (NH*HD)                // 2048
#define KW (NKV*HD)               // 512

// Scratch
__device__ float g_q[SB*QW];
__device__ float g_k[SB*KW];
__device__ float g_v[SB*KW];
__device__ float g_o[SB*QW];

// ---------------------------------------------------------------------------
// tf32 helpers
// ---------------------------------------------------------------------------
__device__ __forceinline__ uint32_t f2tf32(float f) {
    uint32_t r;
    asm("cvt.rna.tf32.f32 %0, %1;" : "=r"(r) : "f"(f));
    return r;
}

// Dekker split: x ~= hi + lo, both tf32-representable
__device__ __forceinline__ void split2(float x, uint32_t& h, uint32_t& l) {
    h = f2tf32(x);
    l = f2tf32(x - __uint_as_float(h));
}

__device__ __forceinline__ void mma_tf32(float* c,
    uint32_t a0, uint32_t a1, uint32_t a2, uint32_t a3,
    uint32_t b0, uint32_t b1)
{
    asm volatile(
        "mma.sync.aligned.m16n8k8.row.col.f32.tf32.tf32.f32 "
        "{%0,%1,%2,%3}, {%4,%5,%6,%7}, {%8,%9}, {%0,%1,%2,%3};"
        : "+f"(c[0]), "+f"(c[1]), "+f"(c[2]), "+f"(c[3])
        : "r"(a0), "r"(a1), "r"(a2), "r"(a3), "r"(b0), "r"(b1));
}

// ---------------------------------------------------------------------------
// tf32 tensor-core GEMM tile (round-7 validated, unchanged)
// ---------------------------------------------------------------------------
#define BK 32
#define SSTR 132

__device__ __forceinline__ void gemm_tc(
    const float* __restrict__ A, int lda,
    const float* __restrict__ B, int ldb,
    float* __restrict__ C, int ldc,
    int K, int m0, int n0)
{
    __shared__ uint32_t As[BK][SSTR];
    __shared__ uint32_t Bs[BK][SSTR];

    const int tid  = threadIdx.x;
    const int lane = tid & 31;
    const int wid  = tid >> 5;
    const int wm   = wid >> 2;
    const int wn   = wid & 3;
    const int g    = lane >> 2;
    const int t    = lane & 3;

    float acc[4][4][4];
#pragma unroll
    for (int mm = 0; mm < 4; mm++)
#pragma unroll
        for (int nn = 0; nn < 4; nn++)
#pragma unroll
            for (int i = 0; i < 4; i++) acc[mm][nn][i] = 0.0f;

    float4 pa[4], pb[4];
#pragma unroll
    for (int i = 0; i < 4; i++) {
        int idx = tid + i * 256;
        int am = idx >> 3, akq = idx & 7;
        pa[i] = *(const float4*)(A + (size_t)(m0 + am) * lda + akq * 4);
        int bk = idx >> 5, bnq = idx & 31;
        pb[i] = *(const float4*)(B + (size_t)bk * ldb + n0 + bnq * 4);
    }

    for (int kt = 0; kt < K; kt += BK) {
#pragma unroll
        for (int i = 0; i < 4; i++) {
            int idx = tid + i * 256;
            int am = idx >> 3, akq = idx & 7;
            As[akq * 4 + 0][am] = f2tf32(pa[i].x);
            As[akq * 4 + 1][am] = f2tf32(pa[i].y);
            As[akq * 4 + 2][am] = f2tf32(pa[i].z);
            As[akq * 4 + 3][am] = f2tf32(pa[i].w);
            int bk = idx >> 5, bnq = idx & 31;
            Bs[bk][bnq * 4 + 0] = f2tf32(pb[i].x);
            Bs[bk][bnq * 4 + 1] = f2tf32(pb[i].y);
            Bs[bk][bnq * 4 + 2] = f2tf32(pb[i].z);
            Bs[bk][bnq * 4 + 3] = f2tf32(pb[i].w);
        }
        __syncthreads();

        if (kt + BK < K) {
#pragma unroll
            for (int i = 0; i < 4; i++) {
                int idx = tid + i * 256;
                int am = idx >> 3, akq = idx & 7;
                pa[i] = *(const float4*)(A + (size_t)(m0 + am) * lda + kt + BK + akq * 4);
                int bk = idx >> 5, bnq = idx & 31;
                pb[i] = *(const float4*)(B + (size_t)(kt + BK + bk) * ldb + n0 + bnq * 4);
            }
        }

#pragma unroll
        for (int ks = 0; ks < BK; ks += 8) {
            uint32_t af[4][4], bf[4][2];
#pragma unroll
            for (int mm = 0; mm < 4; mm++) {
                int mr = wm * 64 + mm * 16 + g;
                af[mm][0] = As[ks + t][mr];
                af[mm][1] = As[ks + t][mr + 8];
                af[mm][2] = As[ks + t + 4][mr];
                af[mm][3] = As[ks + t + 4][mr + 8];
            }
#pragma unroll
            for (int nn = 0; nn < 4; nn++) {
                int nc = wn * 32 + nn * 8 + g;
                bf[nn][0] = Bs[ks + t][nc];
                bf[nn][1] = Bs[ks + t + 4][nc];
            }
#pragma unroll
            for (int mm = 0; mm < 4; mm++)
#pragma unroll
                for (int nn = 0; nn < 4; nn++)
                    mma_tf32(acc[mm][nn], af[mm][0], af[mm][1], af[mm][2], af[mm][3],
                             bf[nn][0], bf[nn][1]);
        }
        __syncthreads();
    }

#pragma unroll
    for (int mm = 0; mm < 4; mm++)
#pragma unroll
        for (int nn = 0; nn < 4; nn++) {
            int row = m0 + wm * 64 + mm * 16 + g;
            int col = n0 + wn * 32 + nn * 8 + t * 2;
            float2 lo = make_float2(acc[mm][nn][0], acc[mm][nn][1]);
            float2 hi = make_float2(acc[mm][nn][2], acc[mm][nn][3]);
            *(float2*)&C[(size_t)row * ldc + col]       = lo;
            *(float2*)&C[(size_t)(row + 8) * ldc + col] = hi;
        }
}

__global__ void __launch_bounds__(256) qkv_kernel(
    const float* __restrict__ x,
    const float* __restrict__ Wq,
    const float* __restrict__ Wk,
    const float* __restrict__ Wv)
{
    int ncol0 = blockIdx.x * 128;
    int m0    = blockIdx.y * 128;
    const float* Bp;
    float* Cp;
    int ldn, n0;
    if (ncol0 < 2048)      { Bp = Wq; Cp = g_q; ldn = QW; n0 = ncol0;        }
    else if (ncol0 < 2560) { Bp = Wk; Cp = g_k; ldn = KW; n0 = ncol0 - 2048; }
    else                   { Bp = Wv; Cp = g_v; ldn = KW; n0 = ncol0 - 2560; }
    gemm_tc(x, DMODEL, Bp, ldn, Cp, ldn, DMODEL, m0, n0);
}

__global__ void __launch_bounds__(256) out_kernel(
    const float* __restrict__ Wo, float* __restrict__ out)
{
    gemm_tc(g_o, QW, Wo, DMODEL, out, DMODEL, QW, blockIdx.y * 128, blockIdx.x * 128);
}

// ---------------------------------------------------------------------------
// RoPE (validated negated angle)
// ---------------------------------------------------------------------------
__global__ void __launch_bounds__(256) rope_kernel(int which)
{
    float* p     = which ? g_k : g_q;
    const int nh = which ? NKV : NH;
    int idx  = blockIdx.x * 256 + threadIdx.x;
    int dd   = idx & 63;
    int rest = idx >> 6;
    int head = rest & (nh - 1);
    int row  = rest / nh;
    if (row >= SB) return;
    int s = row >> 1;

    float e    = (float)(2 * dd) / 128.0f;
    float invf = 1.0f / powf(10000.0f, e);
    float ang  = -(float)s * invf;
    float c, sn;
    sincosf(ang, &c, &sn);

    float* base = p + (size_t)row * (nh * HD) + head * HD;
    float u1 = base[dd];
    float u2 = base[dd + 64];
    base[dd]      = u1 * c - u2 * sn;
    base[dd + 64] = u2 * c + u1 * sn;
}

// ---------------------------------------------------------------------------
// Tensor-core flash attention with split-tf32 (error-compensated).
// Block: 128 q-rows x 64 kv per tile. 8 warps, warp w owns q rows w*16..+15.
// Grid: (16 q-tiles [reversed for load balance], B*H).
// ---------------------------------------------------------------------------
#define QSTR 136     // smem row stride for Q/K/V (fp32 words)
#define PSTR 72      // smem row stride for per-warp P

__global__ void __launch_bounds__(256, 1) flash_tc()
{
    extern __shared__ float sm[];
    float* sQ = sm;                       // [128][QSTR]
    float* sK = sQ + 128 * QSTR;          // [64][QSTR]
    float* sV = sK + 64 * QSTR;           // [64][QSTR]
    float* sP = sV + 64 * QSTR;           // [8][16][PSTR]

    const int qt  = 15 - blockIdx.x;      // big tiles first
    const int bh  = blockIdx.y;
    const int b   = bh >> 4;
    const int h   = bh & 15;
    const int kvh = h >> 2;
    const int tid  = threadIdx.x;
    const int lane = tid & 31;
    const int w    = tid >> 5;
    const int g    = lane >> 2;
    const int t    = lane & 3;

    // Load Q tile (128 x 128)
    for (int idx = tid; idx < 128 * 32; idx += 256) {
        int r  = idx >> 5;
        int c4 = (idx & 31) << 2;
        *(float4*)&sQ[r * QSTR + c4] =
            *(const float4*)&g_q[((size_t)(qt * 128 + r) * BATCH + b) * QW + h * HD + c4];
    }

    float oacc[16][4];
#pragma unroll
    for (int dt = 0; dt < 16; dt++)
#pragma unroll
        for (int i = 0; i < 4; i++) oacc[dt][i] = 0.0f;
    float m0 = -1e30f, m1 = -1e30f, l0 = 0.0f, l1 = 0.0f;

    const float sc = 0.08838834764831845f;   // 1/sqrt(128)
    const int r0 = qt * 128 + w * 16 + g;
    const int r1 = r0 + 8;
    float* pw = sP + w * 16 * PSTR;

    const int nkt = 2 * qt + 2;
    for (int kt = 0; kt < nkt; kt++) {
        __syncthreads();
        // Load K,V tiles (64 x 128 each), row-major
        for (int idx = tid; idx < 64 * 32; idx += 256) {
            int j  = idx >> 5;
            int c4 = (idx & 31) << 2;
            size_t ga = ((size_t)(kt * 64 + j) * BATCH + b) * KW + kvh * HD + c4;
            *(float4*)&sK[j * QSTR + c4] = *(const float4*)&g_k[ga];
            *(float4*)&sV[j * QSTR + c4] = *(const float4*)&g_v[ga];
        }
        __syncthreads();

        // Warp fully masked for this tile? (all its rows < first col)
        if (kt * 64 > qt * 128 + w * 16 + 15) continue;

        // ---- scores: S[16x64] = Q_w @ K^T, split-tf32 (3 mma) ----
        float sacc[8][4];
#pragma unroll
        for (int nt = 0; nt < 8; nt++)
#pragma unroll
            for (int i = 0; i < 4; i++) sacc[nt][i] = 0.0f;

#pragma unroll
        for (int ks = 0; ks < 16; ks++) {
            const float* qb = sQ + (w * 16) * QSTR + ks * 8;
            uint32_t ah[4], al[4];
            split2(qb[g * QSTR + t],            ah[0], al[0]);
            split2(qb[(g + 8) * QSTR + t],      ah[1], al[1]);
            split2(qb[g * QSTR + t + 4],        ah[2], al[2]);
            split2(qb[(g + 8) * QSTR + t + 4],  ah[3], al[3]);
#pragma unroll
            for (int nt = 0; nt < 8; nt++) {
                uint32_t bh0, bl0, bh1, bl1;
                split2(sK[(nt * 8 + g) * QSTR + ks * 8 + t],     bh0, bl0);
                split2(sK[(nt * 8 + g) * QSTR + ks * 8 + t + 4], bh1, bl1);
                mma_tf32(sacc[nt], ah[0], ah[1], ah[2], ah[3], bh0, bh1);
                mma_tf32(sacc[nt], ah[0], ah[1], ah[2], ah[3], bl0, bl1);
                mma_tf32(sacc[nt], al[0], al[1], al[2], al[3], bh0, bh1);
            }
        }

        // ---- scale + mask + online softmax (rows r0, r1 per thread) ----
        const bool need_mask = (kt >= 2 * qt);
        float mx0 = -1e30f, mx1 = -1e30f;
#pragma unroll
        for (int nt = 0; nt < 8; nt++) {
            int c0 = kt * 64 + nt * 8 + 2 * t;
#pragma unroll
            for (int i = 0; i < 4; i++) {
                float v = sacc[nt][i] * sc;
                if (need_mask) {
                    int col = c0 + (i & 1);
                    int row = (i < 2) ? r0 : r1;
                    if (col > row) v = -1e30f;
                }
                sacc[nt][i] = v;
            }
            mx0 = fmaxf(mx0, fmaxf(sacc[nt][0], sacc[nt][1]));
            mx1 = fmaxf(mx1, fmaxf(sacc[nt][2], sacc[nt][3]));
        }
#pragma unroll
        for (int off = 1; off <= 2; off <<= 1) {
            mx0 = fmaxf(mx0, __shfl_xor_sync(0xffffffffu, mx0, off));
            mx1 = fmaxf(mx1, __shfl_xor_sync(0xffffffffu, mx1, off));
        }
        float mn0 = fmaxf(m0, mx0), mn1 = fmaxf(m1, mx1);
        float corr0 = expf(m0 - mn0), corr1 = expf(m1 - mn1);
        m0 = mn0; m1 = mn1;

        float sum0 = 0.0f, sum1 = 0.0f;
#pragma unroll
        for (int nt = 0; nt < 8; nt++) {
            float p00 = expf(sacc[nt][0] - m0);
            float p01 = expf(sacc[nt][1] - m0);
            float p10 = expf(sacc[nt][2] - m1);
            float p11 = expf(sacc[nt][3] - m1);
            sum0 += p00 + p01;
            sum1 += p10 + p11;
            *(float2*)&pw[g * PSTR + nt * 8 + 2 * t]       = make_float2(p00, p01);
            *(float2*)&pw[(g + 8) * PSTR + nt * 8 + 2 * t] = make_float2(p10, p11);
        }
#pragma unroll
        for (int off = 1; off <= 2; off <<= 1) {
            sum0 += __shfl_xor_sync(0xffffffffu, sum0, off);
            sum1 += __shfl_xor_sync(0xffffffffu, sum1, off);
        }
        l0 = l0 * corr0 + sum0;
        l1 = l1 * corr1 + sum1;
#pragma unroll
        for (int dt = 0; dt < 16; dt++) {
            oacc[dt][0] *= corr0; oacc[dt][1] *= corr0;
            oacc[dt][2] *= corr1; oacc[dt][3] *= corr1;
        }
        __syncwarp();

        // ---- O += P @ V, split-tf32 ----
#pragma unroll
        for (int ks = 0; ks < 8; ks++) {
            uint32_t ah[4], al[4];
            split2(pw[g * PSTR + ks * 8 + t],           ah[0], al[0]);
            split2(pw[(g + 8) * PSTR + ks * 8 + t],     ah[1], al[1]);
            split2(pw[g * PSTR + ks * 8 + t + 4],       ah[2], al[2]);
            split2(pw[(g + 8) * PSTR + ks * 8 + t + 4], ah[3], al[3]);
#pragma unroll
            for (int dt = 0; dt < 16; dt++) {
                uint32_t bh0, bl0, bh1, bl1;
                split2(sV[(ks * 8 + t) * QSTR + dt * 8 + g],     bh0, bl0);
                split2(sV[(ks * 8 + t + 4) * QSTR + dt * 8 + g], bh1, bl1);
                mma_tf32(oacc[dt], ah[0], ah[1], ah[2], ah[3], bh0, bh1);
                mma_tf32(oacc[dt], ah[0], ah[1], ah[2], ah[3], bl0, bl1);
                mma_tf32(oacc[dt], al[0], al[1], al[2], al[3], bh0, bh1);
            }
        }
    }

    // ---- epilogue ----
    float invl0 = 1.0f / l0, invl1 = 1.0f / l1;
#pragma unroll
    for (int dt = 0; dt < 16; dt++) {
        int col = h * HD + dt * 8 + 2 * t;
        *(float2*)&g_o[((size_t)r0 * BATCH + b) * QW + col] =
            make_float2(oacc[dt][0] * invl0, oacc[dt][1] * invl0);
        *(float2*)&g_o[((size_t)r1 * BATCH + b) * QW + col] =
            make_float2(oacc[dt][2] * invl1, oacc[dt][3] * invl1);
    }
}

// ---------------------------------------------------------------------------
// Launch
// ---------------------------------------------------------------------------
extern "C" void kernel_launch(void* const* d_in, const int* in_sizes, int n_in,
                              void* d_out, int out_size)
{
    int ix = -1, ik = -1, iv = -1, ia = -1, ib = -1;
    for (int i = 0; i < n_in; i++) {
        if (in_sizes[i] == 8388608) { ix = i; }
        else if (in_sizes[i] == 1048576) { if (ik < 0) ik = i; else iv = i; }
        else if (in_sizes[i] == 4194304) { if (ia < 0) ia = i; else ib = i; }
    }
    int iq, io;
    if (ix == 0) { iq = ia; io = ib; }
    else         { io = ia; iq = ib; }

    const float* x  = (const float*)d_in[ix];
    const float* Wq = (const float*)d_in[iq];
    const float* Wk = (const float*)d_in[ik];
    const float* Wv = (const float*)d_in[iv];
    const float* Wo = (const float*)d_in[io];
    float* out = (float*)d_out;

    qkv_kernel<<<dim3(24, 32), 256>>>(x, Wq, Wk, Wv);

    rope_kernel<<<(SB * NH  * 64) / 256, 256>>>(0);
    rope_kernel<<<(SB * NKV * 64) / 256, 256>>>(1);

    const int FLASH_SMEM = (128 * QSTR + 64 * QSTR + 64 * QSTR + 8 * 16 * PSTR) * (int)sizeof(float);
    cudaFuncSetAttribute(flash_tc, cudaFuncAttributeMaxDynamicSharedMemorySize, FLASH_SMEM);
    flash_tc<<<dim3(16, 32), 256, FLASH_SMEM>>>();

    out_kernel<<<dim3(16, 32), 256>>>(Wo, out);
}

// round 9
// speedup vs baseline: 12.2529x; 1.2232x over previous
#include <cuda_runtime.h>
#include <math.h>
#include <stdint.h>

// Problem constants
#define S_LEN 2048
#define BATCH 2
#define DMODEL 2048
#define NH 16
#define NKV 4
#define HD 128
#define SB (S_LEN*BATCH)
#define QW (NH*HD)
#define KW (NKV*HD)

// Scratch
__device__ float g_q[SB*QW];
__device__ float g_k[SB*KW];
__device__ float g_v[SB*KW];
__device__ float g_o[SB*QW];

// ---------------------------------------------------------------------------
// tf32 helpers
// ---------------------------------------------------------------------------
__device__ __forceinline__ uint32_t f2tf32(float f) {
    uint32_t r;
    asm("cvt.rna.tf32.f32 %0, %1;" : "=r"(r) : "f"(f));
    return r;
}
__device__ __forceinline__ void split2(float x, uint32_t& h, uint32_t& l) {
    h = f2tf32(x);
    l = f2tf32(x - __uint_as_float(h));
}
__device__ __forceinline__ void mma_tf32(float* c,
    uint32_t a0, uint32_t a1, uint32_t a2, uint32_t a3,
    uint32_t b0, uint32_t b1)
{
    asm volatile(
        "mma.sync.aligned.m16n8k8.row.col.f32.tf32.tf32.f32 "
        "{%0,%1,%2,%3}, {%4,%5,%6,%7}, {%8,%9}, {%0,%1,%2,%3};"
        : "+f"(c[0]), "+f"(c[1]), "+f"(c[2]), "+f"(c[3])
        : "r"(a0), "r"(a1), "r"(a2), "r"(a3), "r"(b0), "r"(b1));
}

// ---------------------------------------------------------------------------
// tf32 tensor-core GEMM tile (round-7 validated, unchanged)
// ---------------------------------------------------------------------------
#define BK 32
#define SSTR 132

__device__ __forceinline__ void gemm_tc(
    const float* __restrict__ A, int lda,
    const float* __restrict__ B, int ldb,
    float* __restrict__ C, int ldc,
    int K, int m0, int n0)
{
    __shared__ uint32_t As[BK][SSTR];
    __shared__ uint32_t Bs[BK][SSTR];

    const int tid  = threadIdx.x;
    const int lane = tid & 31;
    const int wid  = tid >> 5;
    const int wm   = wid >> 2;
    const int wn   = wid & 3;
    const int g    = lane >> 2;
    const int t    = lane & 3;

    float acc[4][4][4];
#pragma unroll
    for (int mm = 0; mm < 4; mm++)
#pragma unroll
        for (int nn = 0; nn < 4; nn++)
#pragma unroll
            for (int i = 0; i < 4; i++) acc[mm][nn][i] = 0.0f;

    float4 pa[4], pb[4];
#pragma unroll
    for (int i = 0; i < 4; i++) {
        int idx = tid + i * 256;
        int am = idx >> 3, akq = idx & 7;
        pa[i] = *(const float4*)(A + (size_t)(m0 + am) * lda + akq * 4);
        int bk = idx >> 5, bnq = idx & 31;
        pb[i] = *(const float4*)(B + (size_t)bk * ldb + n0 + bnq * 4);
    }

    for (int kt = 0; kt < K; kt += BK) {
#pragma unroll
        for (int i = 0; i < 4; i++) {
            int idx = tid + i * 256;
            int am = idx >> 3, akq = idx & 7;
            As[akq * 4 + 0][am] = f2tf32(pa[i].x);
            As[akq * 4 + 1][am] = f2tf32(pa[i].y);
            As[akq * 4 + 2][am] = f2tf32(pa[i].z);
            As[akq * 4 + 3][am] = f2tf32(pa[i].w);
            int bk = idx >> 5, bnq = idx & 31;
            Bs[bk][bnq * 4 + 0] = f2tf32(pb[i].x);
            Bs[bk][bnq * 4 + 1] = f2tf32(pb[i].y);
            Bs[bk][bnq * 4 + 2] = f2tf32(pb[i].z);
            Bs[bk][bnq * 4 + 3] = f2tf32(pb[i].w);
        }
        __syncthreads();

        if (kt + BK < K) {
#pragma unroll
            for (int i = 0; i < 4; i++) {
                int idx = tid + i * 256;
                int am = idx >> 3, akq = idx & 7;
                pa[i] = *(const float4*)(A + (size_t)(m0 + am) * lda + kt + BK + akq * 4);
                int bk = idx >> 5, bnq = idx & 31;
                pb[i] = *(const float4*)(B + (size_t)(kt + BK + bk) * ldb + n0 + bnq * 4);
            }
        }

#pragma unroll
        for (int ks = 0; ks < BK; ks += 8) {
            uint32_t af[4][4], bf[4][2];
#pragma unroll
            for (int mm = 0; mm < 4; mm++) {
                int mr = wm * 64 + mm * 16 + g;
                af[mm][0] = As[ks + t][mr];
                af[mm][1] = As[ks + t][mr + 8];
                af[mm][2] = As[ks + t + 4][mr];
                af[mm][3] = As[ks + t + 4][mr + 8];
            }
#pragma unroll
            for (int nn = 0; nn < 4; nn++) {
                int nc = wn * 32 + nn * 8 + g;
                bf[nn][0] = Bs[ks + t][nc];
                bf[nn][1] = Bs[ks + t + 4][nc];
            }
#pragma unroll
            for (int mm = 0; mm < 4; mm++)
#pragma unroll
                for (int nn = 0; nn < 4; nn++)
                    mma_tf32(acc[mm][nn], af[mm][0], af[mm][1], af[mm][2], af[mm][3],
                             bf[nn][0], bf[nn][1]);
        }
        __syncthreads();
    }

#pragma unroll
    for (int mm = 0; mm < 4; mm++)
#pragma unroll
        for (int nn = 0; nn < 4; nn++) {
            int row = m0 + wm * 64 + mm * 16 + g;
            int col = n0 + wn * 32 + nn * 8 + t * 2;
            float2 lo = make_float2(acc[mm][nn][0], acc[mm][nn][1]);
            float2 hi = make_float2(acc[mm][nn][2], acc[mm][nn][3]);
            *(float2*)&C[(size_t)row * ldc + col]       = lo;
            *(float2*)&C[(size_t)(row + 8) * ldc + col] = hi;
        }
}

__global__ void __launch_bounds__(256) qkv_kernel(
    const float* __restrict__ x,
    const float* __restrict__ Wq,
    const float* __restrict__ Wk,
    const float* __restrict__ Wv)
{
    int ncol0 = blockIdx.x * 128;
    int m0    = blockIdx.y * 128;
    const float* Bp;
    float* Cp;
    int ldn, n0;
    if (ncol0 < 2048)      { Bp = Wq; Cp = g_q; ldn = QW; n0 = ncol0;        }
    else if (ncol0 < 2560) { Bp = Wk; Cp = g_k; ldn = KW; n0 = ncol0 - 2048; }
    else                   { Bp = Wv; Cp = g_v; ldn = KW; n0 = ncol0 - 2560; }
    gemm_tc(x, DMODEL, Bp, ldn, Cp, ldn, DMODEL, m0, n0);
}

__global__ void __launch_bounds__(256) out_kernel(
    const float* __restrict__ Wo, float* __restrict__ out)
{
    gemm_tc(g_o, QW, Wo, DMODEL, out, DMODEL, QW, blockIdx.y * 128, blockIdx.x * 128);
}

// ---------------------------------------------------------------------------
// RoPE (validated negated angle)
// ---------------------------------------------------------------------------
__global__ void __launch_bounds__(256) rope_kernel(int which)
{
    float* p     = which ? g_k : g_q;
    const int nh = which ? NKV : NH;
    int idx  = blockIdx.x * 256 + threadIdx.x;
    int dd   = idx & 63;
    int rest = idx >> 6;
    int head = rest & (nh - 1);
    int row  = rest / nh;
    if (row >= SB) return;
    int s = row >> 1;

    float e    = (float)(2 * dd) / 128.0f;
    float invf = 1.0f / powf(10000.0f, e);
    float ang  = -(float)s * invf;
    float c, sn;
    sincosf(ang, &c, &sn);

    float* base = p + (size_t)row * (nh * HD) + head * HD;
    float u1 = base[dd];
    float u2 = base[dd + 64];
    base[dd]      = u1 * c - u2 * sn;
    base[dd + 64] = u2 * c + u1 * sn;
}

// ---------------------------------------------------------------------------
// Tensor-core flash attention, v2:
//  - K split hi/lo cooperatively at load (once per tile, not per consumer)
//  - QK^T: 3-mma split-tf32 (precision-critical)
//  - P@V: single tf32 (P,V stored as tf32 in smem)
//  - conflict-free strides: Q/K/P stride ≡4 (mod 32), V stride ≡8
// Block: 128 q-rows x 64 kv-tile, 8 warps, warp owns 16 q rows.
// ---------------------------------------------------------------------------
#define QSTR 132
#define KSTR 132
#define VSTR 136
#define PSTR 68

__global__ void __launch_bounds__(256, 1) flash_tc()
{
    extern __shared__ uint32_t smu[];
    float*    sQ  = (float*)smu;              // [128][QSTR] fp32
    uint32_t* sKh = smu + 128 * QSTR;         // [64][KSTR] tf32 hi
    uint32_t* sKl = sKh + 64 * KSTR;          // [64][KSTR] tf32 lo
    uint32_t* sV  = sKl + 64 * KSTR;          // [64][VSTR] tf32
    uint32_t* sP  = sV  + 64 * VSTR;          // [8][16][PSTR] tf32

    const int qt  = 15 - blockIdx.x;
    const int bh  = blockIdx.y;
    const int b   = bh >> 4;
    const int h   = bh & 15;
    const int kvh = h >> 2;
    const int tid  = threadIdx.x;
    const int lane = tid & 31;
    const int w    = tid >> 5;
    const int g    = lane >> 2;
    const int t    = lane & 3;

    // Load Q tile (128 x 128), fp32
    for (int idx = tid; idx < 128 * 32; idx += 256) {
        int r  = idx >> 5;
        int c4 = (idx & 31) << 2;
        *(float4*)&sQ[r * QSTR + c4] =
            *(const float4*)&g_q[((size_t)(qt * 128 + r) * BATCH + b) * QW + h * HD + c4];
    }

    float oacc[16][4];
#pragma unroll
    for (int dt = 0; dt < 16; dt++)
#pragma unroll
        for (int i = 0; i < 4; i++) oacc[dt][i] = 0.0f;
    float m0 = -1e30f, m1 = -1e30f, l0 = 0.0f, l1 = 0.0f;

    const float sc = 0.08838834764831845f;
    const int r0 = qt * 128 + w * 16 + g;
    const int r1 = r0 + 8;
    uint32_t* pw = sP + w * 16 * PSTR;

    const int nkt = 2 * qt + 2;
    for (int kt = 0; kt < nkt; kt++) {
        __syncthreads();
        // Load K (split hi/lo) and V (tf32) cooperatively
        for (int idx = tid; idx < 64 * 32; idx += 256) {
            int j  = idx >> 5;
            int c4 = (idx & 31) << 2;
            size_t ga = ((size_t)(kt * 64 + j) * BATCH + b) * KW + kvh * HD + c4;
            float4 vk = *(const float4*)&g_k[ga];
            float4 vv = *(const float4*)&g_v[ga];
            uint32_t hh, ll;
            split2(vk.x, hh, ll); sKh[j*KSTR + c4    ] = hh; sKl[j*KSTR + c4    ] = ll;
            split2(vk.y, hh, ll); sKh[j*KSTR + c4 + 1] = hh; sKl[j*KSTR + c4 + 1] = ll;
            split2(vk.z, hh, ll); sKh[j*KSTR + c4 + 2] = hh; sKl[j*KSTR + c4 + 2] = ll;
            split2(vk.w, hh, ll); sKh[j*KSTR + c4 + 3] = hh; sKl[j*KSTR + c4 + 3] = ll;
            sV[j*VSTR + c4    ] = f2tf32(vv.x);
            sV[j*VSTR + c4 + 1] = f2tf32(vv.y);
            sV[j*VSTR + c4 + 2] = f2tf32(vv.z);
            sV[j*VSTR + c4 + 3] = f2tf32(vv.w);
        }
        __syncthreads();

        if (kt * 64 > qt * 128 + w * 16 + 15) continue;   // fully masked warp

        // ---- scores: S[16x64] = Q_w @ K^T, split-tf32 ----
        float sacc[8][4];
#pragma unroll
        for (int nt = 0; nt < 8; nt++)
#pragma unroll
            for (int i = 0; i < 4; i++) sacc[nt][i] = 0.0f;

#pragma unroll
        for (int ks = 0; ks < 16; ks++) {
            const float* qb = sQ + (w * 16) * QSTR + ks * 8;
            uint32_t ah[4], al[4];
            split2(qb[g * QSTR + t],            ah[0], al[0]);
            split2(qb[(g + 8) * QSTR + t],      ah[1], al[1]);
            split2(qb[g * QSTR + t + 4],        ah[2], al[2]);
            split2(qb[(g + 8) * QSTR + t + 4],  ah[3], al[3]);
#pragma unroll
            for (int nt = 0; nt < 8; nt++) {
                const uint32_t* kbh = sKh + (nt * 8 + g) * KSTR + ks * 8;
                const uint32_t* kbl = sKl + (nt * 8 + g) * KSTR + ks * 8;
                uint32_t bh0 = kbh[t], bh1 = kbh[t + 4];
                uint32_t bl0 = kbl[t], bl1 = kbl[t + 4];
                mma_tf32(sacc[nt], ah[0], ah[1], ah[2], ah[3], bh0, bh1);
                mma_tf32(sacc[nt], ah[0], ah[1], ah[2], ah[3], bl0, bl1);
                mma_tf32(sacc[nt], al[0], al[1], al[2], al[3], bh0, bh1);
            }
        }

        // ---- scale + mask + online softmax ----
        const bool need_mask = (kt >= 2 * qt);
        float mx0 = -1e30f, mx1 = -1e30f;
#pragma unroll
        for (int nt = 0; nt < 8; nt++) {
            int c0 = kt * 64 + nt * 8 + 2 * t;
#pragma unroll
            for (int i = 0; i < 4; i++) {
                float v = sacc[nt][i] * sc;
                if (need_mask) {
                    int col = c0 + (i & 1);
                    int row = (i < 2) ? r0 : r1;
                    if (col > row) v = -1e30f;
                }
                sacc[nt][i] = v;
            }
            mx0 = fmaxf(mx0, fmaxf(sacc[nt][0], sacc[nt][1]));
            mx1 = fmaxf(mx1, fmaxf(sacc[nt][2], sacc[nt][3]));
        }
#pragma unroll
        for (int off = 1; off <= 2; off <<= 1) {
            mx0 = fmaxf(mx0, __shfl_xor_sync(0xffffffffu, mx0, off));
            mx1 = fmaxf(mx1, __shfl_xor_sync(0xffffffffu, mx1, off));
        }
        float mn0 = fmaxf(m0, mx0), mn1 = fmaxf(m1, mx1);
        float corr0 = expf(m0 - mn0), corr1 = expf(m1 - mn1);
        m0 = mn0; m1 = mn1;

        float sum0 = 0.0f, sum1 = 0.0f;
#pragma unroll
        for (int nt = 0; nt < 8; nt++) {
            float p00 = expf(sacc[nt][0] - m0);
            float p01 = expf(sacc[nt][1] - m0);
            float p10 = expf(sacc[nt][2] - m1);
            float p11 = expf(sacc[nt][3] - m1);
            sum0 += p00 + p01;
            sum1 += p10 + p11;
            *(uint2*)&pw[g * PSTR + nt * 8 + 2 * t] =
                make_uint2(f2tf32(p00), f2tf32(p01));
            *(uint2*)&pw[(g + 8) * PSTR + nt * 8 + 2 * t] =
                make_uint2(f2tf32(p10), f2tf32(p11));
        }
#pragma unroll
        for (int off = 1; off <= 2; off <<= 1) {
            sum0 += __shfl_xor_sync(0xffffffffu, sum0, off);
            sum1 += __shfl_xor_sync(0xffffffffu, sum1, off);
        }
        l0 = l0 * corr0 + sum0;
        l1 = l1 * corr1 + sum1;
#pragma unroll
        for (int dt = 0; dt < 16; dt++) {
            oacc[dt][0] *= corr0; oacc[dt][1] *= corr0;
            oacc[dt][2] *= corr1; oacc[dt][3] *= corr1;
        }
        __syncwarp();

        // ---- O += P @ V, single tf32 ----
#pragma unroll
        for (int ks = 0; ks < 8; ks++) {
            uint32_t a0 = pw[g * PSTR + ks * 8 + t];
            uint32_t a1 = pw[(g + 8) * PSTR + ks * 8 + t];
            uint32_t a2 = pw[g * PSTR + ks * 8 + t + 4];
            uint32_t a3 = pw[(g + 8) * PSTR + ks * 8 + t + 4];
#pragma unroll
            for (int dt = 0; dt < 16; dt++) {
                uint32_t b0 = sV[(ks * 8 + t) * VSTR + dt * 8 + g];
                uint32_t b1 = sV[(ks * 8 + t + 4) * VSTR + dt * 8 + g];
                mma_tf32(oacc[dt], a0, a1, a2, a3, b0, b1);
            }
        }
    }

    // ---- epilogue ----
    float invl0 = 1.0f / l0, invl1 = 1.0f / l1;
#pragma unroll
    for (int dt = 0; dt < 16; dt++) {
        int col = h * HD + dt * 8 + 2 * t;
        *(float2*)&g_o[((size_t)r0 * BATCH + b) * QW + col] =
            make_float2(oacc[dt][0] * invl0, oacc[dt][1] * invl0);
        *(float2*)&g_o[((size_t)r1 * BATCH + b) * QW + col] =
            make_float2(oacc[dt][2] * invl1, oacc[dt][3] * invl1);
    }
}

// ---------------------------------------------------------------------------
// Launch
// ---------------------------------------------------------------------------
extern "C" void kernel_launch(void* const* d_in, const int* in_sizes, int n_in,
                              void* d_out, int out_size)
{
    int ix = -1, ik = -1, iv = -1, ia = -1, ib = -1;
    for (int i = 0; i < n_in; i++) {
        if (in_sizes[i] == 8388608) { ix = i; }
        else if (in_sizes[i] == 1048576) { if (ik < 0) ik = i; else iv = i; }
        else if (in_sizes[i] == 4194304) { if (ia < 0) ia = i; else ib = i; }
    }
    int iq, io;
    if (ix == 0) { iq = ia; io = ib; }
    else         { io = ia; iq = ib; }

    const float* x  = (const float*)d_in[ix];
    const float* Wq = (const float*)d_in[iq];
    const float* Wk = (const float*)d_in[ik];
    const float* Wv = (const float*)d_in[iv];
    const float* Wo = (const float*)d_in[io];
    float* out = (float*)d_out;

    qkv_kernel<<<dim3(24, 32), 256>>>(x, Wq, Wk, Wv);

    rope_kernel<<<(SB * NH  * 64) / 256, 256>>>(0);
    rope_kernel<<<(SB * NKV * 64) / 256, 256>>>(1);

    const int FLASH_SMEM =
        (128 * QSTR + 2 * 64 * KSTR + 64 * VSTR + 8 * 16 * PSTR) * (int)sizeof(uint32_t);
    cudaFuncSetAttribute(flash_tc, cudaFuncAttributeMaxDynamicSharedMemorySize, FLASH_SMEM);
    flash_tc<<<dim3(16, 32), 256, FLASH_SMEM>>>();

    out_kernel<<<dim3(16, 32), 256>>>(Wo, out);
}

// round 10
// speedup vs baseline: 14.2032x; 1.1592x over previous
#include <cuda_runtime.h>
#include <cuda_bf16.h>
#include <math.h>
#include <stdint.h>

// Problem constants
#define S_LEN 2048
#define BATCH 2
#define DMODEL 2048
#define NH 16
#define NKV 4
#define HD 128
#define SB (S_LEN*BATCH)
#define QW (NH*HD)
#define KW (NKV*HD)

// Scratch
__device__ float g_q[SB*QW];
__device__ float g_k[SB*KW];
__device__ float g_v[SB*KW];
__device__ float g_o[SB*QW];

// ---------------------------------------------------------------------------
// helpers
// ---------------------------------------------------------------------------
__device__ __forceinline__ uint32_t f2tf32(float f) {
    uint32_t r;
    asm("cvt.rna.tf32.f32 %0, %1;" : "=r"(r) : "f"(f));
    return r;
}
__device__ __forceinline__ void split2(float x, uint32_t& h, uint32_t& l) {
    h = f2tf32(x);
    l = f2tf32(x - __uint_as_float(h));
}
// bf16 hi/lo split
__device__ __forceinline__ void splitb(float x, __nv_bfloat16& h, __nv_bfloat16& l) {
    h = __float2bfloat16(x);
    l = __float2bfloat16(x - __bfloat162float(h));
}
__device__ __forceinline__ uint32_t packb(__nv_bfloat16 lo_k, __nv_bfloat16 hi_k) {
    __nv_bfloat162 p = __halves2bfloat162(lo_k, hi_k);   // .x = first k (low 16)
    return *(uint32_t*)&p;
}

__device__ __forceinline__ void mma_tf32(float* c,
    uint32_t a0, uint32_t a1, uint32_t a2, uint32_t a3,
    uint32_t b0, uint32_t b1)
{
    asm volatile(
        "mma.sync.aligned.m16n8k8.row.col.f32.tf32.tf32.f32 "
        "{%0,%1,%2,%3}, {%4,%5,%6,%7}, {%8,%9}, {%0,%1,%2,%3};"
        : "+f"(c[0]), "+f"(c[1]), "+f"(c[2]), "+f"(c[3])
        : "r"(a0), "r"(a1), "r"(a2), "r"(a3), "r"(b0), "r"(b1));
}
__device__ __forceinline__ void mma_bf16(float* c,
    uint32_t a0, uint32_t a1, uint32_t a2, uint32_t a3,
    uint32_t b0, uint32_t b1)
{
    asm volatile(
        "mma.sync.aligned.m16n8k16.row.col.f32.bf16.bf16.f32 "
        "{%0,%1,%2,%3}, {%4,%5,%6,%7}, {%8,%9}, {%0,%1,%2,%3};"
        : "+f"(c[0]), "+f"(c[1]), "+f"(c[2]), "+f"(c[3])
        : "r"(a0), "r"(a1), "r"(a2), "r"(a3), "r"(b0), "r"(b1));
}

// ---------------------------------------------------------------------------
// tf32 tensor-core GEMM tile (validated, unchanged)
// ---------------------------------------------------------------------------
#define BK 32
#define SSTR 132

__device__ __forceinline__ void gemm_tc(
    const float* __restrict__ A, int lda,
    const float* __restrict__ B, int ldb,
    float* __restrict__ C, int ldc,
    int K, int m0, int n0)
{
    __shared__ uint32_t As[BK][SSTR];
    __shared__ uint32_t Bs[BK][SSTR];

    const int tid  = threadIdx.x;
    const int lane = tid & 31;
    const int wid  = tid >> 5;
    const int wm   = wid >> 2;
    const int wn   = wid & 3;
    const int g    = lane >> 2;
    const int t    = lane & 3;

    float acc[4][4][4];
#pragma unroll
    for (int mm = 0; mm < 4; mm++)
#pragma unroll
        for (int nn = 0; nn < 4; nn++)
#pragma unroll
            for (int i = 0; i < 4; i++) acc[mm][nn][i] = 0.0f;

    float4 pa[4], pb[4];
#pragma unroll
    for (int i = 0; i < 4; i++) {
        int idx = tid + i * 256;
        int am = idx >> 3, akq = idx & 7;
        pa[i] = *(const float4*)(A + (size_t)(m0 + am) * lda + akq * 4);
        int bk = idx >> 5, bnq = idx & 31;
        pb[i] = *(const float4*)(B + (size_t)bk * ldb + n0 + bnq * 4);
    }

    for (int kt = 0; kt < K; kt += BK) {
#pragma unroll
        for (int i = 0; i < 4; i++) {
            int idx = tid + i * 256;
            int am = idx >> 3, akq = idx & 7;
            As[akq * 4 + 0][am] = f2tf32(pa[i].x);
            As[akq * 4 + 1][am] = f2tf32(pa[i].y);
            As[akq * 4 + 2][am] = f2tf32(pa[i].z);
            As[akq * 4 + 3][am] = f2tf32(pa[i].w);
            int bk = idx >> 5, bnq = idx & 31;
            Bs[bk][bnq * 4 + 0] = f2tf32(pb[i].x);
            Bs[bk][bnq * 4 + 1] = f2tf32(pb[i].y);
            Bs[bk][bnq * 4 + 2] = f2tf32(pb[i].z);
            Bs[bk][bnq * 4 + 3] = f2tf32(pb[i].w);
        }
        __syncthreads();

        if (kt + BK < K) {
#pragma unroll
            for (int i = 0; i < 4; i++) {
                int idx = tid + i * 256;
                int am = idx >> 3, akq = idx & 7;
                pa[i] = *(const float4*)(A + (size_t)(m0 + am) * lda + kt + BK + akq * 4);
                int bk = idx >> 5, bnq = idx & 31;
                pb[i] = *(const float4*)(B + (size_t)(kt + BK + bk) * ldb + n0 + bnq * 4);
            }
        }

#pragma unroll
        for (int ks = 0; ks < BK; ks += 8) {
            uint32_t af[4][4], bf[4][2];
#pragma unroll
            for (int mm = 0; mm < 4; mm++) {
                int mr = wm * 64 + mm * 16 + g;
                af[mm][0] = As[ks + t][mr];
                af[mm][1] = As[ks + t][mr + 8];
                af[mm][2] = As[ks + t + 4][mr];
                af[mm][3] = As[ks + t + 4][mr + 8];
            }
#pragma unroll
            for (int nn = 0; nn < 4; nn++) {
                int nc = wn * 32 + nn * 8 + g;
                bf[nn][0] = Bs[ks + t][nc];
                bf[nn][1] = Bs[ks + t + 4][nc];
            }
#pragma unroll
            for (int mm = 0; mm < 4; mm++)
#pragma unroll
                for (int nn = 0; nn < 4; nn++)
                    mma_tf32(acc[mm][nn], af[mm][0], af[mm][1], af[mm][2], af[mm][3],
                             bf[nn][0], bf[nn][1]);
        }
        __syncthreads();
    }

#pragma unroll
    for (int mm = 0; mm < 4; mm++)
#pragma unroll
        for (int nn = 0; nn < 4; nn++) {
            int row = m0 + wm * 64 + mm * 16 + g;
            int col = n0 + wn * 32 + nn * 8 + t * 2;
            float2 lo = make_float2(acc[mm][nn][0], acc[mm][nn][1]);
            float2 hi = make_float2(acc[mm][nn][2], acc[mm][nn][3]);
            *(float2*)&C[(size_t)row * ldc + col]       = lo;
            *(float2*)&C[(size_t)(row + 8) * ldc + col] = hi;
        }
}

__global__ void __launch_bounds__(256) qkv_kernel(
    const float* __restrict__ x,
    const float* __restrict__ Wq,
    const float* __restrict__ Wk,
    const float* __restrict__ Wv)
{
    int ncol0 = blockIdx.x * 128;
    int m0    = blockIdx.y * 128;
    const float* Bp;
    float* Cp;
    int ldn, n0;
    if (ncol0 < 2048)      { Bp = Wq; Cp = g_q; ldn = QW; n0 = ncol0;        }
    else if (ncol0 < 2560) { Bp = Wk; Cp = g_k; ldn = KW; n0 = ncol0 - 2048; }
    else                   { Bp = Wv; Cp = g_v; ldn = KW; n0 = ncol0 - 2560; }
    gemm_tc(x, DMODEL, Bp, ldn, Cp, ldn, DMODEL, m0, n0);
}

__global__ void __launch_bounds__(256) out_kernel(
    const float* __restrict__ Wo, float* __restrict__ out)
{
    gemm_tc(g_o, QW, Wo, DMODEL, out, DMODEL, QW, blockIdx.y * 128, blockIdx.x * 128);
}

// ---------------------------------------------------------------------------
// RoPE (validated negated angle)
// ---------------------------------------------------------------------------
__global__ void __launch_bounds__(256) rope_kernel(int which)
{
    float* p     = which ? g_k : g_q;
    const int nh = which ? NKV : NH;
    int idx  = blockIdx.x * 256 + threadIdx.x;
    int dd   = idx & 63;
    int rest = idx >> 6;
    int head = rest & (nh - 1);
    int row  = rest / nh;
    if (row >= SB) return;
    int s = row >> 1;

    float e    = (float)(2 * dd) / 128.0f;
    float invf = 1.0f / powf(10000.0f, e);
    float ang  = -(float)s * invf;
    float c, sn;
    sincosf(ang, &c, &sn);

    float* base = p + (size_t)row * (nh * HD) + head * HD;
    float u1 = base[dd];
    float u2 = base[dd + 64];
    base[dd]      = u1 * c - u2 * sn;
    base[dd + 64] = u2 * c + u1 * sn;
}

// ---------------------------------------------------------------------------
// Flash attention v3:
//  - QK^T: split-bf16 3-term, m16n8k16 (Q,K pre-split hi/lo, packed bf16x2
//    along k: smem word = k-pair, stride 68 (≡4 mod 32, conflict-free))
//  - P@V: single tf32 (unchanged, validated)
//  - K/V register-prefetch pipeline (hide L2 latency behind compute)
// Block: 128 q-rows x 64 kv-tile, 8 warps, warp owns 16 q rows.
// ---------------------------------------------------------------------------
#define BSTR 68      // bf16-pair row stride (words)
#define VSTR 136     // V tf32 row stride
#define PSTR 68      // P tf32 row stride

__global__ void __launch_bounds__(256, 1) flash_tc()
{
    extern __shared__ uint32_t smu[];
    uint32_t* sQh = smu;                      // [128][BSTR] bf16x2 hi
    uint32_t* sQl = sQh + 128 * BSTR;         // [128][BSTR] bf16x2 lo
    uint32_t* sKh = sQl + 128 * BSTR;         // [64][BSTR]
    uint32_t* sKl = sKh + 64 * BSTR;          // [64][BSTR]
    uint32_t* sV  = sKl + 64 * BSTR;          // [64][VSTR] tf32
    uint32_t* sP  = sV  + 64 * VSTR;          // [8][16][PSTR] tf32

    const int qt  = 15 - blockIdx.x;
    const int bh  = blockIdx.y;
    const int b   = bh >> 4;
    const int h   = bh & 15;
    const int kvh = h >> 2;
    const int tid  = threadIdx.x;
    const int lane = tid & 31;
    const int w    = tid >> 5;
    const int g    = lane >> 2;
    const int t    = lane & 3;

    // Load + split + pack Q tile (128 x 128)
    for (int idx = tid; idx < 128 * 32; idx += 256) {
        int r  = idx >> 5;
        int c4 = (idx & 31) << 2;
        float4 q = *(const float4*)&g_q[((size_t)(qt * 128 + r) * BATCH + b) * QW + h * HD + c4];
        __nv_bfloat16 xh, xl, yh, yl, zh, zl, wh, wl;
        splitb(q.x, xh, xl); splitb(q.y, yh, yl);
        splitb(q.z, zh, zl); splitb(q.w, wh, wl);
        int p0 = r * BSTR + (c4 >> 1);
        sQh[p0]     = packb(xh, yh);
        sQh[p0 + 1] = packb(zh, wh);
        sQl[p0]     = packb(xl, yl);
        sQl[p0 + 1] = packb(zl, wl);
    }

    float oacc[16][4];
#pragma unroll
    for (int dt = 0; dt < 16; dt++)
#pragma unroll
        for (int i = 0; i < 4; i++) oacc[dt][i] = 0.0f;
    float m0 = -1e30f, m1 = -1e30f, l0 = 0.0f, l1 = 0.0f;

    const float sc = 0.08838834764831845f;
    const int r0 = qt * 128 + w * 16 + g;
    const int r1 = r0 + 8;
    uint32_t* pw = sP + w * 16 * PSTR;

    const int nkt = 2 * qt + 2;

    // prefetch tile 0
    float4 pk[8], pv[8];
#pragma unroll
    for (int i = 0; i < 8; i++) {
        int idx = tid + i * 256;
        int j  = idx >> 5;
        int c4 = (idx & 31) << 2;
        size_t ga = ((size_t)j * BATCH + b) * KW + kvh * HD + c4;
        pk[i] = *(const float4*)&g_k[ga];
        pv[i] = *(const float4*)&g_v[ga];
    }

    for (int kt = 0; kt < nkt; kt++) {
        __syncthreads();
        // commit prefetched K (split bf16) and V (tf32) to smem
#pragma unroll
        for (int i = 0; i < 8; i++) {
            int idx = tid + i * 256;
            int j  = idx >> 5;
            int c4 = (idx & 31) << 2;
            __nv_bfloat16 xh, xl, yh, yl, zh, zl, wh, wl;
            splitb(pk[i].x, xh, xl); splitb(pk[i].y, yh, yl);
            splitb(pk[i].z, zh, zl); splitb(pk[i].w, wh, wl);
            int p0 = j * BSTR + (c4 >> 1);
            sKh[p0]     = packb(xh, yh);
            sKh[p0 + 1] = packb(zh, wh);
            sKl[p0]     = packb(xl, yl);
            sKl[p0 + 1] = packb(zl, wl);
            sV[j * VSTR + c4    ] = f2tf32(pv[i].x);
            sV[j * VSTR + c4 + 1] = f2tf32(pv[i].y);
            sV[j * VSTR + c4 + 2] = f2tf32(pv[i].z);
            sV[j * VSTR + c4 + 3] = f2tf32(pv[i].w);
        }
        __syncthreads();

        // prefetch next tile while computing
        if (kt + 1 < nkt) {
#pragma unroll
            for (int i = 0; i < 8; i++) {
                int idx = tid + i * 256;
                int j  = idx >> 5;
                int c4 = (idx & 31) << 2;
                size_t ga = ((size_t)((kt + 1) * 64 + j) * BATCH + b) * KW + kvh * HD + c4;
                pk[i] = *(const float4*)&g_k[ga];
                pv[i] = *(const float4*)&g_v[ga];
            }
        }

        if (kt * 64 <= qt * 128 + w * 16 + 15) {   // warp not fully masked
            // ---- scores: S[16x64] = Q_w @ K^T, split-bf16 3-term, k16 ----
            float sacc[8][4];
#pragma unroll
            for (int nt = 0; nt < 8; nt++)
#pragma unroll
                for (int i = 0; i < 4; i++) sacc[nt][i] = 0.0f;

#pragma unroll
            for (int ks = 0; ks < 8; ks++) {
                const int qb = (w * 16) * BSTR + ks * 8;
                uint32_t ah0 = sQh[qb + g * BSTR + t];
                uint32_t ah1 = sQh[qb + (g + 8) * BSTR + t];
                uint32_t ah2 = sQh[qb + g * BSTR + t + 4];
                uint32_t ah3 = sQh[qb + (g + 8) * BSTR + t + 4];
                uint32_t al0 = sQl[qb + g * BSTR + t];
                uint32_t al1 = sQl[qb + (g + 8) * BSTR + t];
                uint32_t al2 = sQl[qb + g * BSTR + t + 4];
                uint32_t al3 = sQl[qb + (g + 8) * BSTR + t + 4];
#pragma unroll
                for (int nt = 0; nt < 8; nt++) {
                    const int kb = (nt * 8 + g) * BSTR + ks * 8;
                    uint32_t bh0 = sKh[kb + t], bh1 = sKh[kb + t + 4];
                    uint32_t bl0 = sKl[kb + t], bl1 = sKl[kb + t + 4];
                    mma_bf16(sacc[nt], ah0, ah1, ah2, ah3, bh0, bh1);
                    mma_bf16(sacc[nt], ah0, ah1, ah2, ah3, bl0, bl1);
                    mma_bf16(sacc[nt], al0, al1, al2, al3, bh0, bh1);
                }
            }

            // ---- scale + mask + online softmax ----
            const bool need_mask = (kt >= 2 * qt);
            float mx0 = -1e30f, mx1 = -1e30f;
#pragma unroll
            for (int nt = 0; nt < 8; nt++) {
                int c0 = kt * 64 + nt * 8 + 2 * t;
#pragma unroll
                for (int i = 0; i < 4; i++) {
                    float v = sacc[nt][i] * sc;
                    if (need_mask) {
                        int col = c0 + (i & 1);
                        int row = (i < 2) ? r0 : r1;
                        if (col > row) v = -1e30f;
                    }
                    sacc[nt][i] = v;
                }
                mx0 = fmaxf(mx0, fmaxf(sacc[nt][0], sacc[nt][1]));
                mx1 = fmaxf(mx1, fmaxf(sacc[nt][2], sacc[nt][3]));
            }
#pragma unroll
            for (int off = 1; off <= 2; off <<= 1) {
                mx0 = fmaxf(mx0, __shfl_xor_sync(0xffffffffu, mx0, off));
                mx1 = fmaxf(mx1, __shfl_xor_sync(0xffffffffu, mx1, off));
            }
            float mn0 = fmaxf(m0, mx0), mn1 = fmaxf(m1, mx1);
            float corr0 = expf(m0 - mn0), corr1 = expf(m1 - mn1);
            m0 = mn0; m1 = mn1;

            float sum0 = 0.0f, sum1 = 0.0f;
#pragma unroll
            for (int nt = 0; nt < 8; nt++) {
                float p00 = expf(sacc[nt][0] - m0);
                float p01 = expf(sacc[nt][1] - m0);
                float p10 = expf(sacc[nt][2] - m1);
                float p11 = expf(sacc[nt][3] - m1);
                sum0 += p00 + p01;
                sum1 += p10 + p11;
                *(uint2*)&pw[g * PSTR + nt * 8 + 2 * t] =
                    make_uint2(f2tf32(p00), f2tf32(p01));
                *(uint2*)&pw[(g + 8) * PSTR + nt * 8 + 2 * t] =
                    make_uint2(f2tf32(p10), f2tf32(p11));
            }
#pragma unroll
            for (int off = 1; off <= 2; off <<= 1) {
                sum0 += __shfl_xor_sync(0xffffffffu, sum0, off);
                sum1 += __shfl_xor_sync(0xffffffffu, sum1, off);
            }
            l0 = l0 * corr0 + sum0;
            l1 = l1 * corr1 + sum1;
#pragma unroll
            for (int dt = 0; dt < 16; dt++) {
                oacc[dt][0] *= corr0; oacc[dt][1] *= corr0;
                oacc[dt][2] *= corr1; oacc[dt][3] *= corr1;
            }
            __syncwarp();

            // ---- O += P @ V, single tf32 ----
#pragma unroll
            for (int ks = 0; ks < 8; ks++) {
                uint32_t a0 = pw[g * PSTR + ks * 8 + t];
                uint32_t a1 = pw[(g + 8) * PSTR + ks * 8 + t];
                uint32_t a2 = pw[g * PSTR + ks * 8 + t + 4];
                uint32_t a3 = pw[(g + 8) * PSTR + ks * 8 + t + 4];
#pragma unroll
                for (int dt = 0; dt < 16; dt++) {
                    uint32_t b0 = sV[(ks * 8 + t) * VSTR + dt * 8 + g];
                    uint32_t b1 = sV[(ks * 8 + t + 4) * VSTR + dt * 8 + g];
                    mma_tf32(oacc[dt], a0, a1, a2, a3, b0, b1);
                }
            }
        }
    }

    // ---- epilogue ----
    float invl0 = 1.0f / l0, invl1 = 1.0f / l1;
#pragma unroll
    for (int dt = 0; dt < 16; dt++) {
        int col = h * HD + dt * 8 + 2 * t;
        *(float2*)&g_o[((size_t)r0 * BATCH + b) * QW + col] =
            make_float2(oacc[dt][0] * invl0, oacc[dt][1] * invl0);
        *(float2*)&g_o[((size_t)r1 * BATCH + b) * QW + col] =
            make_float2(oacc[dt][2] * invl1, oacc[dt][3] * invl1);
    }
}

// ---------------------------------------------------------------------------
// Launch
// ---------------------------------------------------------------------------
extern "C" void kernel_launch(void* const* d_in, const int* in_sizes, int n_in,
                              void* d_out, int out_size)
{
    int ix = -1, ik = -1, iv = -1, ia = -1, ib = -1;
    for (int i = 0; i < n_in; i++) {
        if (in_sizes[i] == 8388608) { ix = i; }
        else if (in_sizes[i] == 1048576) { if (ik < 0) ik = i; else iv = i; }
        else if (in_sizes[i] == 4194304) { if (ia < 0) ia = i; else ib = i; }
    }
    int iq, io;
    if (ix == 0) { iq = ia; io = ib; }
    else         { io = ia; iq = ib; }

    const float* x  = (const float*)d_in[ix];
    const float* Wq = (const float*)d_in[iq];
    const float* Wk = (const float*)d_in[ik];
    const float* Wv = (const float*)d_in[iv];
    const float* Wo = (const float*)d_in[io];
    float* out = (float*)d_out;

    qkv_kernel<<<dim3(24, 32), 256>>>(x, Wq, Wk, Wv);

    rope_kernel<<<(SB * NH  * 64) / 256, 256>>>(0);
    rope_kernel<<<(SB * NKV * 64) / 256, 256>>>(1);

    const int FLASH_SMEM =
        (2 * 128 * BSTR + 2 * 64 * BSTR + 64 * VSTR + 8 * 16 * PSTR) * (int)sizeof(uint32_t);
    cudaFuncSetAttribute(flash_tc, cudaFuncAttributeMaxDynamicSharedMemorySize, FLASH_SMEM);
    flash_tc<<<dim3(16, 32), 256, FLASH_SMEM>>>();

    out_kernel<<<dim3(16, 32), 256>>>(Wo, out);
}

// round 11
// speedup vs baseline: 22.9382x; 1.6150x over previous
#include <cuda_runtime.h>
#include <cuda_bf16.h>
#include <cuda_fp16.h>
#include <math.h>
#include <stdint.h>

// Problem constants
#define S_LEN 2048
#define BATCH 2
#define DMODEL 2048
#define NH 16
#define NKV 4
#define HD 128
#define SB (S_LEN*BATCH)
#define QW (NH*HD)
#define KW (NKV*HD)
#define KP_TOT 1024              // 2048 k / 2 per pair

// Scratch
__device__ float g_q[SB*QW];
__device__ float g_k[SB*KW];
__device__ float g_v[SB*KW];
__device__ float g_o[SB*QW];
// fp16-packed operands
__device__ uint32_t g_xP [SB*KP_TOT];
__device__ uint32_t g_oP [SB*KP_TOT];
__device__ uint32_t g_WqT[2048*KP_TOT];
__device__ uint32_t g_WkT[ 512*KP_TOT];
__device__ uint32_t g_WvT[ 512*KP_TOT];
__device__ uint32_t g_WoT[2048*KP_TOT];

// ---------------------------------------------------------------------------
// helpers
// ---------------------------------------------------------------------------
__device__ __forceinline__ uint32_t f2tf32(float f) {
    uint32_t r;
    asm("cvt.rna.tf32.f32 %0, %1;" : "=r"(r) : "f"(f));
    return r;
}
__device__ __forceinline__ void splitb(float x, __nv_bfloat16& h, __nv_bfloat16& l) {
    h = __float2bfloat16(x);
    l = __float2bfloat16(x - __bfloat162float(h));
}
__device__ __forceinline__ uint32_t packb(__nv_bfloat16 lo_k, __nv_bfloat16 hi_k) {
    __nv_bfloat162 p = __halves2bfloat162(lo_k, hi_k);
    return *(uint32_t*)&p;
}
__device__ __forceinline__ uint32_t packh(float a, float b) {
    __half2 h = __floats2half2_rn(a, b);   // .x = a (low bits) = even k
    return *(uint32_t*)&h;
}

__device__ __forceinline__ void mma_tf32(float* c,
    uint32_t a0, uint32_t a1, uint32_t a2, uint32_t a3,
    uint32_t b0, uint32_t b1)
{
    asm volatile(
        "mma.sync.aligned.m16n8k8.row.col.f32.tf32.tf32.f32 "
        "{%0,%1,%2,%3}, {%4,%5,%6,%7}, {%8,%9}, {%0,%1,%2,%3};"
        : "+f"(c[0]), "+f"(c[1]), "+f"(c[2]), "+f"(c[3])
        : "r"(a0), "r"(a1), "r"(a2), "r"(a3), "r"(b0), "r"(b1));
}
__device__ __forceinline__ void mma_bf16(float* c,
    uint32_t a0, uint32_t a1, uint32_t a2, uint32_t a3,
    uint32_t b0, uint32_t b1)
{
    asm volatile(
        "mma.sync.aligned.m16n8k16.row.col.f32.bf16.bf16.f32 "
        "{%0,%1,%2,%3}, {%4,%5,%6,%7}, {%8,%9}, {%0,%1,%2,%3};"
        : "+f"(c[0]), "+f"(c[1]), "+f"(c[2]), "+f"(c[3])
        : "r"(a0), "r"(a1), "r"(a2), "r"(a3), "r"(b0), "r"(b1));
}
__device__ __forceinline__ void mma_fp16(float* c,
    uint32_t a0, uint32_t a1, uint32_t a2, uint32_t a3,
    uint32_t b0, uint32_t b1)
{
    asm volatile(
        "mma.sync.aligned.m16n8k16.row.col.f32.f16.f16.f32 "
        "{%0,%1,%2,%3}, {%4,%5,%6,%7}, {%8,%9}, {%0,%1,%2,%3};"
        : "+f"(c[0]), "+f"(c[1]), "+f"(c[2]), "+f"(c[3])
        : "r"(a0), "r"(a1), "r"(a2), "r"(a3), "r"(b0), "r"(b1));
}

// ---------------------------------------------------------------------------
// prep kernels
// ---------------------------------------------------------------------------
// pack fp32 row-major [rows][2048] -> fp16x2 [rows][1024]
__global__ void __launch_bounds__(256) pack_h2(
    const float* __restrict__ src, uint32_t* __restrict__ dst, int n4)
{
    int i = blockIdx.x * 256 + threadIdx.x;
    if (i >= n4) return;
    float4 v = ((const float4*)src)[i];
    ((uint2*)dst)[i] = make_uint2(packh(v.x, v.y), packh(v.z, v.w));
}

// transpose W[K=2048][N] -> WT[n][kpair] fp16x2, 64x64 tiles
__global__ void __launch_bounds__(256) transpose_pack(
    const float* __restrict__ W, uint32_t* __restrict__ WT, int N)
{
    __shared__ float sm[64][68];
    const int n0 = blockIdx.x * 64;
    const int k0 = blockIdx.y * 64;
    const int tid = threadIdx.x;
#pragma unroll
    for (int i = 0; i < 4; i++) {
        int idx = tid + i * 256;
        int kr = idx >> 4;
        int nq = idx & 15;
        float4 v = *(const float4*)&W[(size_t)(k0 + kr) * N + n0 + nq * 4];
        sm[kr][nq * 4 + 0] = v.x;
        sm[kr][nq * 4 + 1] = v.y;
        sm[kr][nq * 4 + 2] = v.z;
        sm[kr][nq * 4 + 3] = v.w;
    }
    __syncthreads();
    const int kp = tid & 31;
    const int nb = tid >> 5;
#pragma unroll
    for (int ph = 0; ph < 8; ph++) {
        int n = nb + ph * 8;
        WT[(size_t)(n0 + n) * KP_TOT + (k0 >> 1) + kp] =
            packh(sm[2 * kp][n], sm[2 * kp + 1][n]);
    }
}

// ---------------------------------------------------------------------------
// fp16 tensor-core GEMM tile: C[m0..+128, n0..+128] = A @ B^T(packed)
// Ap: [M][KP_TOT] fp16x2 (k-pairs), Bp: [N][KP_TOT] fp16x2.
// 8 warps (2m x 4n), m16n8k16, BK=32 (16 kpairs/iter), K=2048.
// ---------------------------------------------------------------------------
#define FSTR 36

__device__ __forceinline__ void gemm_fp16_tile(
    const uint32_t* __restrict__ Ap, const uint32_t* __restrict__ Bp,
    float* __restrict__ C, int ldc, int m0, int n0)
{
    __shared__ uint32_t As[128][FSTR];
    __shared__ uint32_t Bs[128][FSTR];

    const int tid  = threadIdx.x;
    const int lane = tid & 31;
    const int wid  = tid >> 5;
    const int wm   = wid >> 2;
    const int wn   = wid & 3;
    const int g    = lane >> 2;
    const int t    = lane & 3;

    float acc[4][4][4];
#pragma unroll
    for (int mm = 0; mm < 4; mm++)
#pragma unroll
        for (int nn = 0; nn < 4; nn++)
#pragma unroll
            for (int i = 0; i < 4; i++) acc[mm][nn][i] = 0.0f;

    uint4 pa[2], pb[2];
#pragma unroll
    for (int i = 0; i < 2; i++) {
        int idx = tid + i * 256;
        int r = idx >> 2, u = idx & 3;
        pa[i] = *(const uint4*)&Ap[(size_t)(m0 + r) * KP_TOT + u * 4];
        pb[i] = *(const uint4*)&Bp[(size_t)(n0 + r) * KP_TOT + u * 4];
    }

    for (int kt = 0; kt < 64; kt++) {
#pragma unroll
        for (int i = 0; i < 2; i++) {
            int idx = tid + i * 256;
            int r = idx >> 2, u = idx & 3;
            *(uint4*)&As[r][u * 4] = pa[i];
            *(uint4*)&Bs[r][u * 4] = pb[i];
        }
        __syncthreads();

        if (kt + 1 < 64) {
#pragma unroll
            for (int i = 0; i < 2; i++) {
                int idx = tid + i * 256;
                int r = idx >> 2, u = idx & 3;
                pa[i] = *(const uint4*)&Ap[(size_t)(m0 + r) * KP_TOT + (kt + 1) * 16 + u * 4];
                pb[i] = *(const uint4*)&Bp[(size_t)(n0 + r) * KP_TOT + (kt + 1) * 16 + u * 4];
            }
        }

#pragma unroll
        for (int ks = 0; ks < 2; ks++) {
            const int ko = ks * 8;
            uint32_t af[4][4], bf2[4][2];
#pragma unroll
            for (int mm = 0; mm < 4; mm++) {
                int rb = wm * 64 + mm * 16 + g;
                af[mm][0] = As[rb][ko + t];
                af[mm][1] = As[rb + 8][ko + t];
                af[mm][2] = As[rb][ko + t + 4];
                af[mm][3] = As[rb + 8][ko + t + 4];
            }
#pragma unroll
            for (int nn = 0; nn < 4; nn++) {
                int cb = wn * 32 + nn * 8 + g;
                bf2[nn][0] = Bs[cb][ko + t];
                bf2[nn][1] = Bs[cb][ko + t + 4];
            }
#pragma unroll
            for (int mm = 0; mm < 4; mm++)
#pragma unroll
                for (int nn = 0; nn < 4; nn++)
                    mma_fp16(acc[mm][nn], af[mm][0], af[mm][1], af[mm][2], af[mm][3],
                             bf2[nn][0], bf2[nn][1]);
        }
        __syncthreads();
    }

#pragma unroll
    for (int mm = 0; mm < 4; mm++)
#pragma unroll
        for (int nn = 0; nn < 4; nn++) {
            int row = m0 + wm * 64 + mm * 16 + g;
            int col = n0 + wn * 32 + nn * 8 + t * 2;
            *(float2*)&C[(size_t)row * ldc + col] =
                make_float2(acc[mm][nn][0], acc[mm][nn][1]);
            *(float2*)&C[(size_t)(row + 8) * ldc + col] =
                make_float2(acc[mm][nn][2], acc[mm][nn][3]);
        }
}

__global__ void __launch_bounds__(256) qkv_fp16()
{
    int ncol0 = blockIdx.x * 128;
    int m0    = blockIdx.y * 128;
    const uint32_t* Bp;
    float* Cp;
    int ldc, n0;
    if (ncol0 < 2048)      { Bp = g_WqT; Cp = g_q; ldc = QW; n0 = ncol0;        }
    else if (ncol0 < 2560) { Bp = g_WkT; Cp = g_k; ldc = KW; n0 = ncol0 - 2048; }
    else                   { Bp = g_WvT; Cp = g_v; ldc = KW; n0 = ncol0 - 2560; }
    gemm_fp16_tile(g_xP, Bp, Cp, ldc, m0, n0);
}

__global__ void __launch_bounds__(256) out_fp16(float* __restrict__ out)
{
    gemm_fp16_tile(g_oP, g_WoT, out, DMODEL, blockIdx.y * 128, blockIdx.x * 128);
}

// ---------------------------------------------------------------------------
// RoPE (validated negated angle)
// ---------------------------------------------------------------------------
__global__ void __launch_bounds__(256) rope_kernel(int which)
{
    float* p     = which ? g_k : g_q;
    const int nh = which ? NKV : NH;
    int idx  = blockIdx.x * 256 + threadIdx.x;
    int dd   = idx & 63;
    int rest = idx >> 6;
    int head = rest & (nh - 1);
    int row  = rest / nh;
    if (row >= SB) return;
    int s = row >> 1;

    float e    = (float)(2 * dd) / 128.0f;
    float invf = 1.0f / powf(10000.0f, e);
    float ang  = -(float)s * invf;
    float c, sn;
    sincosf(ang, &c, &sn);

    float* base = p + (size_t)row * (nh * HD) + head * HD;
    float u1 = base[dd];
    float u2 = base[dd + 64];
    base[dd]      = u1 * c - u2 * sn;
    base[dd + 64] = u2 * c + u1 * sn;
}

// ---------------------------------------------------------------------------
// Flash attention v3 (round-10 validated, unchanged)
// ---------------------------------------------------------------------------
#define BSTR 68
#define VSTR 136
#define PSTR 68

__global__ void __launch_bounds__(256, 1) flash_tc()
{
    extern __shared__ uint32_t smu[];
    uint32_t* sQh = smu;
    uint32_t* sQl = sQh + 128 * BSTR;
    uint32_t* sKh = sQl + 128 * BSTR;
    uint32_t* sKl = sKh + 64 * BSTR;
    uint32_t* sV  = sKl + 64 * BSTR;
    uint32_t* sP  = sV  + 64 * VSTR;

    const int qt  = 15 - blockIdx.x;
    const int bh  = blockIdx.y;
    const int b   = bh >> 4;
    const int h   = bh & 15;
    const int kvh = h >> 2;
    const int tid  = threadIdx.x;
    const int lane = tid & 31;
    const int w    = tid >> 5;
    const int g    = lane >> 2;
    const int t    = lane & 3;

    for (int idx = tid; idx < 128 * 32; idx += 256) {
        int r  = idx >> 5;
        int c4 = (idx & 31) << 2;
        float4 q = *(const float4*)&g_q[((size_t)(qt * 128 + r) * BATCH + b) * QW + h * HD + c4];
        __nv_bfloat16 xh, xl, yh, yl, zh, zl, wh, wl;
        splitb(q.x, xh, xl); splitb(q.y, yh, yl);
        splitb(q.z, zh, zl); splitb(q.w, wh, wl);
        int p0 = r * BSTR + (c4 >> 1);
        sQh[p0]     = packb(xh, yh);
        sQh[p0 + 1] = packb(zh, wh);
        sQl[p0]     = packb(xl, yl);
        sQl[p0 + 1] = packb(zl, wl);
    }

    float oacc[16][4];
#pragma unroll
    for (int dt = 0; dt < 16; dt++)
#pragma unroll
        for (int i = 0; i < 4; i++) oacc[dt][i] = 0.0f;
    float m0 = -1e30f, m1 = -1e30f, l0 = 0.0f, l1 = 0.0f;

    const float sc = 0.08838834764831845f;
    const int r0 = qt * 128 + w * 16 + g;
    const int r1 = r0 + 8;
    uint32_t* pw = sP + w * 16 * PSTR;

    const int nkt = 2 * qt + 2;

    float4 pk[8], pv[8];
#pragma unroll
    for (int i = 0; i < 8; i++) {
        int idx = tid + i * 256;
        int j  = idx >> 5;
        int c4 = (idx & 31) << 2;
        size_t ga = ((size_t)j * BATCH + b) * KW + kvh * HD + c4;
        pk[i] = *(const float4*)&g_k[ga];
        pv[i] = *(const float4*)&g_v[ga];
    }

    for (int kt = 0; kt < nkt; kt++) {
        __syncthreads();
#pragma unroll
        for (int i = 0; i < 8; i++) {
            int idx = tid + i * 256;
            int j  = idx >> 5;
            int c4 = (idx & 31) << 2;
            __nv_bfloat16 xh, xl, yh, yl, zh, zl, wh, wl;
            splitb(pk[i].x, xh, xl); splitb(pk[i].y, yh, yl);
            splitb(pk[i].z, zh, zl); splitb(pk[i].w, wh, wl);
            int p0 = j * BSTR + (c4 >> 1);
            sKh[p0]     = packb(xh, yh);
            sKh[p0 + 1] = packb(zh, wh);
            sKl[p0]     = packb(xl, yl);
            sKl[p0 + 1] = packb(zl, wl);
            sV[j * VSTR + c4    ] = f2tf32(pv[i].x);
            sV[j * VSTR + c4 + 1] = f2tf32(pv[i].y);
            sV[j * VSTR + c4 + 2] = f2tf32(pv[i].z);
            sV[j * VSTR + c4 + 3] = f2tf32(pv[i].w);
        }
        __syncthreads();

        if (kt + 1 < nkt) {
#pragma unroll
            for (int i = 0; i < 8; i++) {
                int idx = tid + i * 256;
                int j  = idx >> 5;
                int c4 = (idx & 31) << 2;
                size_t ga = ((size_t)((kt + 1) * 64 + j) * BATCH + b) * KW + kvh * HD + c4;
                pk[i] = *(const float4*)&g_k[ga];
                pv[i] = *(const float4*)&g_v[ga];
            }
        }

        if (kt * 64 <= qt * 128 + w * 16 + 15) {
            float sacc[8][4];
#pragma unroll
            for (int nt = 0; nt < 8; nt++)
#pragma unroll
                for (int i = 0; i < 4; i++) sacc[nt][i] = 0.0f;

#pragma unroll
            for (int ks = 0; ks < 8; ks++) {
                const int qb = (w * 16) * BSTR + ks * 8;
                uint32_t ah0 = sQh[qb + g * BSTR + t];
                uint32_t ah1 = sQh[qb + (g + 8) * BSTR + t];
                uint32_t ah2 = sQh[qb + g * BSTR + t + 4];
                uint32_t ah3 = sQh[qb + (g + 8) * BSTR + t + 4];
                uint32_t al0 = sQl[qb + g * BSTR + t];
                uint32_t al1 = sQl[qb + (g + 8) * BSTR + t];
                uint32_t al2 = sQl[qb + g * BSTR + t + 4];
                uint32_t al3 = sQl[qb + (g + 8) * BSTR + t + 4];
#pragma unroll
                for (int nt = 0; nt < 8; nt++) {
                    const int kb = (nt * 8 + g) * BSTR + ks * 8;
                    uint32_t bh0 = sKh[kb + t], bh1 = sKh[kb + t + 4];
                    uint32_t bl0 = sKl[kb + t], bl1 = sKl[kb + t + 4];
                    mma_bf16(sacc[nt], ah0, ah1, ah2, ah3, bh0, bh1);
                    mma_bf16(sacc[nt], ah0, ah1, ah2, ah3, bl0, bl1);
                    mma_bf16(sacc[nt], al0, al1, al2, al3, bh0, bh1);
                }
            }

            const bool need_mask = (kt >= 2 * qt);
            float mx0 = -1e30f, mx1 = -1e30f;
#pragma unroll
            for (int nt = 0; nt < 8; nt++) {
                int c0 = kt * 64 + nt * 8 + 2 * t;
#pragma unroll
                for (int i = 0; i < 4; i++) {
                    float v = sacc[nt][i] * sc;
                    if (need_mask) {
                        int col = c0 + (i & 1);
                        int row = (i < 2) ? r0 : r1;
                        if (col > row) v = -1e30f;
                    }
                    sacc[nt][i] = v;
                }
                mx0 = fmaxf(mx0, fmaxf(sacc[nt][0], sacc[nt][1]));
                mx1 = fmaxf(mx1, fmaxf(sacc[nt][2], sacc[nt][3]));
            }
#pragma unroll
            for (int off = 1; off <= 2; off <<= 1) {
                mx0 = fmaxf(mx0, __shfl_xor_sync(0xffffffffu, mx0, off));
                mx1 = fmaxf(mx1, __shfl_xor_sync(0xffffffffu, mx1, off));
            }
            float mn0 = fmaxf(m0, mx0), mn1 = fmaxf(m1, mx1);
            float corr0 = expf(m0 - mn0), corr1 = expf(m1 - mn1);
            m0 = mn0; m1 = mn1;

            float sum0 = 0.0f, sum1 = 0.0f;
#pragma unroll
            for (int nt = 0; nt < 8; nt++) {
                float p00 = expf(sacc[nt][0] - m0);
                float p01 = expf(sacc[nt][1] - m0);
                float p10 = expf(sacc[nt][2] - m1);
                float p11 = expf(sacc[nt][3] - m1);
                sum0 += p00 + p01;
                sum1 += p10 + p11;
                *(uint2*)&pw[g * PSTR + nt * 8 + 2 * t] =
                    make_uint2(f2tf32(p00), f2tf32(p01));
                *(uint2*)&pw[(g + 8) * PSTR + nt * 8 + 2 * t] =
                    make_uint2(f2tf32(p10), f2tf32(p11));
            }
#pragma unroll
            for (int off = 1; off <= 2; off <<= 1) {
                sum0 += __shfl_xor_sync(0xffffffffu, sum0, off);
                sum1 += __shfl_xor_sync(0xffffffffu, sum1, off);
            }
            l0 = l0 * corr0 + sum0;
            l1 = l1 * corr1 + sum1;
#pragma unroll
            for (int dt = 0; dt < 16; dt++) {
                oacc[dt][0] *= corr0; oacc[dt][1] *= corr0;
                oacc[dt][2] *= corr1; oacc[dt][3] *= corr1;
            }
            __syncwarp();

#pragma unroll
            for (int ks = 0; ks < 8; ks++) {
                uint32_t a0 = pw[g * PSTR + ks * 8 + t];
                uint32_t a1 = pw[(g + 8) * PSTR + ks * 8 + t];
                uint32_t a2 = pw[g * PSTR + ks * 8 + t + 4];
                uint32_t a3 = pw[(g + 8) * PSTR + ks * 8 + t + 4];
#pragma unroll
                for (int dt = 0; dt < 16; dt++) {
                    uint32_t b0 = sV[(ks * 8 + t) * VSTR + dt * 8 + g];
                    uint32_t b1 = sV[(ks * 8 + t + 4) * VSTR + dt * 8 + g];
                    mma_tf32(oacc[dt], a0, a1, a2, a3, b0, b1);
                }
            }
        }
    }

    float invl0 = 1.0f / l0, invl1 = 1.0f / l1;
#pragma unroll
    for (int dt = 0; dt < 16; dt++) {
        int col = h * HD + dt * 8 + 2 * t;
        *(float2*)&g_o[((size_t)r0 * BATCH + b) * QW + col] =
            make_float2(oacc[dt][0] * invl0, oacc[dt][1] * invl0);
        *(float2*)&g_o[((size_t)r1 * BATCH + b) * QW + col] =
            make_float2(oacc[dt][2] * invl1, oacc[dt][3] * invl1);
    }
}

// ---------------------------------------------------------------------------
// Launch
// ---------------------------------------------------------------------------
extern "C" void kernel_launch(void* const* d_in, const int* in_sizes, int n_in,
                              void* d_out, int out_size)
{
    int ix = -1, ik = -1, iv = -1, ia = -1, ib = -1;
    for (int i = 0; i < n_in; i++) {
        if (in_sizes[i] == 8388608) { ix = i; }
        else if (in_sizes[i] == 1048576) { if (ik < 0) ik = i; else iv = i; }
        else if (in_sizes[i] == 4194304) { if (ia < 0) ia = i; else ib = i; }
    }
    int iq, io;
    if (ix == 0) { iq = ia; io = ib; }
    else         { io = ia; iq = ib; }

    const float* x  = (const float*)d_in[ix];
    const float* Wq = (const float*)d_in[iq];
    const float* Wk = (const float*)d_in[ik];
    const float* Wv = (const float*)d_in[iv];
    const float* Wo = (const float*)d_in[io];
    float* out = (float*)d_out;

    float* go;     cudaGetSymbolAddress((void**)&go,  g_o);
    uint32_t* xP;  cudaGetSymbolAddress((void**)&xP,  g_xP);
    uint32_t* oP;  cudaGetSymbolAddress((void**)&oP,  g_oP);
    uint32_t* WqT; cudaGetSymbolAddress((void**)&WqT, g_WqT);
    uint32_t* WkT; cudaGetSymbolAddress((void**)&WkT, g_WkT);
    uint32_t* WvT; cudaGetSymbolAddress((void**)&WvT, g_WvT);
    uint32_t* WoT; cudaGetSymbolAddress((void**)&WoT, g_WoT);

    const int N4 = SB * DMODEL / 4;
    pack_h2<<<(N4 + 255) / 256, 256>>>(x, xP, N4);
    transpose_pack<<<dim3(32, 32), 256>>>(Wq, WqT, 2048);
    transpose_pack<<<dim3( 8, 32), 256>>>(Wk, WkT,  512);
    transpose_pack<<<dim3( 8, 32), 256>>>(Wv, WvT,  512);
    transpose_pack<<<dim3(32, 32), 256>>>(Wo, WoT, 2048);

    qkv_fp16<<<dim3(24, 32), 256>>>();

    rope_kernel<<<(SB * NH  * 64) / 256, 256>>>(0);
    rope_kernel<<<(SB * NKV * 64) / 256, 256>>>(1);

    const int FLASH_SMEM =
        (2 * 128 * BSTR + 2 * 64 * BSTR + 64 * VSTR + 8 * 16 * PSTR) * (int)sizeof(uint32_t);
    cudaFuncSetAttribute(flash_tc, cudaFuncAttributeMaxDynamicSharedMemorySize, FLASH_SMEM);
    flash_tc<<<dim3(16, 32), 256, FLASH_SMEM>>>();

    pack_h2<<<(N4 + 255) / 256, 256>>>(go, oP, N4);
    out_fp16<<<dim3(16, 32), 256>>>(out);
}